// round 12
// baseline (speedup 1.0000x reference)
#include <cuda_runtime.h>
#include <cuda_bf16.h>
#include <cstdint>
#include <math_constants.h>

// Problem constants
#define BSZ   2
#define SEQ   2048
#define DIMM  1024
#define HEADS 16
#define HD    64
#define MROWS (BSZ*SEQ)      // 4096
#define QKVN  (3*DIMM)       // 3072
#define BH    (BSZ*HEADS)    // 32

// Scratch (device globals: allocation-free rule)
__device__ __nv_bfloat16 g_x_h [MROWS*DIMM], g_x_l [MROWS*DIMM];   // split x
__device__ __nv_bfloat16 g_wq_h[QKVN*DIMM],  g_wq_l[QKVN*DIMM];    // split W_qkv
__device__ __nv_bfloat16 g_wo_h[DIMM*DIMM],  g_wo_l[DIMM*DIMM];    // split W_out
__device__ __nv_bfloat16 g_q_h [BH*SEQ*HD],  g_q_l [BH*SEQ*HD];    // [bh][n][d], x1/8
__device__ __nv_bfloat16 g_k_h [BH*SEQ*HD],  g_k_l [BH*SEQ*HD];    // [bh][n][d]
__device__ __nv_bfloat16 g_vT_h[BH*HD*SEQ],  g_vT_l[BH*HD*SEQ];    // [bh][d][n]
__device__ __nv_bfloat16 g_ao_h[MROWS*DIMM], g_ao_l[MROWS*DIMM];   // [b*n][h*64+d]

// ---------------------------------------------------------------------------
// helpers
// ---------------------------------------------------------------------------
__device__ __forceinline__ uint32_t smem_u32(const void* p) {
    uint32_t a;
    asm("{ .reg .u64 t; cvta.to.shared.u64 t, %1; cvt.u32.u64 %0, t; }"
        : "=r"(a) : "l"(p));
    return a;
}
__device__ __forceinline__ void cp16(uint32_t dst, const void* src) {
    asm volatile("cp.async.cg.shared.global [%0], [%1], 16;"
                 :: "r"(dst), "l"(src) : "memory");
}
#define CP_COMMIT() asm volatile("cp.async.commit_group;" ::: "memory")
#define CP_WAIT(n)  asm volatile("cp.async.wait_group %0;" :: "n"(n) : "memory")

__device__ __forceinline__ void ldsm4(uint32_t& r0, uint32_t& r1, uint32_t& r2,
                                      uint32_t& r3, uint32_t a) {
    asm volatile("ldmatrix.sync.aligned.m8n8.x4.shared.b16 {%0,%1,%2,%3}, [%4];"
                 : "=r"(r0), "=r"(r1), "=r"(r2), "=r"(r3) : "r"(a));
}
// mma m16n8k16 bf16: D(f32) += A(bf16) * B(bf16)
__device__ __forceinline__ void mma16(float* c, const uint32_t* a, const uint32_t* b) {
    asm volatile(
        "mma.sync.aligned.m16n8k16.row.col.f32.bf16.bf16.f32 "
        "{%0,%1,%2,%3},{%4,%5,%6,%7},{%8,%9},{%0,%1,%2,%3};"
        : "+f"(c[0]), "+f"(c[1]), "+f"(c[2]), "+f"(c[3])
        : "r"(a[0]), "r"(a[1]), "r"(a[2]), "r"(a[3]), "r"(b[0]), "r"(b[1]));
}
__device__ __forceinline__ uint32_t sw128(uint32_t o) { return o ^ ((o >> 3) & 0x70); }

// pack two floats to bf16x2: x0 -> lower 16 bits (k even), x1 -> upper
__device__ __forceinline__ uint32_t packbf(float x0, float x1) {
    uint32_t d;
    asm("cvt.rn.bf16x2.f32 %0, %1, %2;" : "=r"(d) : "f"(x1), "f"(x0));
    return d;
}
// split pair: h = bf16x2(hi parts), l = bf16x2(residuals)
__device__ __forceinline__ void split2(float x0, float x1, uint32_t& h, uint32_t& l) {
    h = packbf(x0, x1);
    float f0 = __uint_as_float(h << 16);
    float f1 = __uint_as_float(h & 0xFFFF0000u);
    l = packbf(x0 - f0, x1 - f1);
}

// ---------------------------------------------------------------------------
// Pre-split: fp32 -> bf16 hi/lo planes (grid-stride over float4)
// ---------------------------------------------------------------------------
__global__ void split_kernel(const float* __restrict__ src,
                             __nv_bfloat16* __restrict__ dh,
                             __nv_bfloat16* __restrict__ dl, int n4)
{
    int i = blockIdx.x * blockDim.x + threadIdx.x;
    if (i >= n4) return;
    float4 v = ((const float4*)src)[i];
    uint32_t h0, l0, h1, l1;
    split2(v.x, v.y, h0, l0);
    split2(v.z, v.w, h1, l1);
    uint2 hh = { h0, h1 }, ll = { l0, l1 };
    ((uint2*)dh)[i] = hh;
    ((uint2*)dl)[i] = ll;
}

// ---------------------------------------------------------------------------
// 3xBF16 GEMM (pre-split inputs): C[m,e] = sum_k A[m,k]*W[e,k] + bias[e]
// 128x128 tile, K-tile 32, 4-stage cp.async, 512 threads (4x4 warps, 32x32
// warp tile, acc 32 regs/thread). Term-major MMA ordering.
// MODE 0: scatter bf16 hi/lo into g_q/g_k/g_vT.  MODE 1: C = out (fp32).
// ---------------------------------------------------------------------------
#define GSTG      32768
#define GSTAGES   4
#define GEMM_SMEM (GSTAGES * GSTG)        // 128KB (also reused as Ds 128x129 f32)

template<int MODE>
__global__ __launch_bounds__(512, 1) void gemm_tc(
    const __nv_bfloat16* __restrict__ Ah, const __nv_bfloat16* __restrict__ Al,
    const __nv_bfloat16* __restrict__ Bh, const __nv_bfloat16* __restrict__ Bl,
    const float* __restrict__ bias, float* __restrict__ C)
{
    extern __shared__ float smem_f[];
    const uint32_t base = smem_u32(smem_f);
    const int t = threadIdx.x, lane = t & 31, wid = t >> 5;   // wid 0..15
    const int wm = wid >> 2, wn = wid & 3;      // 4 x 4 warp grid, 32x32 tiles
    const int m0 = blockIdx.y * 128, n0 = blockIdx.x * 128;

    auto stage_load = [&](int kt) {
        uint32_t S = base + (kt & (GSTAGES - 1)) * GSTG;
        int r = t >> 2, c = t & 3;               // row 0..127, 16B col 0..3
        size_t ao = (size_t)(m0 + r) * DIMM + kt * 32 + c * 8;
        size_t bo = (size_t)(n0 + r) * DIMM + kt * 32 + c * 8;
        uint32_t swh = sw128((uint32_t)(r * 128 + c * 16));
        uint32_t swl = sw128((uint32_t)(r * 128 + 64 + c * 16));
        cp16(S + swh, Ah + ao);
        cp16(S + swl, Al + ao);
        cp16(S + 16384 + swh, Bh + bo);
        cp16(S + 16384 + swl, Bl + bo);
        CP_COMMIT();
    };

    float acc[2][4][4];
    #pragma unroll
    for (int mt = 0; mt < 2; mt++)
        #pragma unroll
        for (int nt = 0; nt < 4; nt++)
            #pragma unroll
            for (int i = 0; i < 4; i++) acc[mt][nt][i] = 0.0f;

    stage_load(0);
    stage_load(1);
    stage_load(2);

    const int KT = DIMM / 32;   // 32
    for (int kt = 0; kt < KT; ++kt) {
        if (kt < KT - 2)       CP_WAIT(2);
        else if (kt == KT - 2) CP_WAIT(1);
        else                   CP_WAIT(0);
        __syncthreads();

        uint32_t sA = base + (kt & (GSTAGES - 1)) * GSTG, sB = sA + 16384;
        #pragma unroll
        for (int cc = 0; cc < 2; ++cc) {        // k16 chunks
            uint32_t ah[2][4], al[2][4];
            #pragma unroll
            for (int mt = 0; mt < 2; mt++) {
                int row = wm * 32 + mt * 16 + (lane & 15);
                uint32_t bc = cc * 32 + (lane >> 4) * 16;
                ldsm4(ah[mt][0], ah[mt][1], ah[mt][2], ah[mt][3],
                      sA + sw128((uint32_t)(row * 128) + bc));
                ldsm4(al[mt][0], al[mt][1], al[mt][2], al[mt][3],
                      sA + sw128((uint32_t)(row * 128) + 64 + bc));
            }
            uint32_t bh4[2][4], bl4[2][4];
            #pragma unroll
            for (int g = 0; g < 2; g++) {
                int row = wn * 32 + g * 16 + (lane & 7) + ((lane & 16) ? 8 : 0);
                uint32_t bc = cc * 32 + ((lane & 8) ? 16 : 0);
                ldsm4(bh4[g][0], bh4[g][1], bh4[g][2], bh4[g][3],
                      sB + sw128((uint32_t)(row * 128) + bc));
                ldsm4(bl4[g][0], bl4[g][1], bl4[g][2], bl4[g][3],
                      sB + sw128((uint32_t)(row * 128) + 64 + bc));
            }
            // term-major: hi*hi over all 8 accs, then lo*hi, then hi*lo
            #pragma unroll
            for (int g = 0; g < 2; g++)
                #pragma unroll
                for (int mt = 0; mt < 2; mt++) {
                    mma16(acc[mt][2*g],     ah[mt], bh4[g]);
                    mma16(acc[mt][2*g + 1], ah[mt], bh4[g] + 2);
                }
            #pragma unroll
            for (int g = 0; g < 2; g++)
                #pragma unroll
                for (int mt = 0; mt < 2; mt++) {
                    mma16(acc[mt][2*g],     al[mt], bh4[g]);
                    mma16(acc[mt][2*g + 1], al[mt], bh4[g] + 2);
                }
            #pragma unroll
            for (int g = 0; g < 2; g++)
                #pragma unroll
                for (int mt = 0; mt < 2; mt++) {
                    mma16(acc[mt][2*g],     ah[mt], bl4[g]);
                    mma16(acc[mt][2*g + 1], ah[mt], bl4[g] + 2);
                }
        }
        if (kt + 3 < KT) stage_load(kt + 3);
    }

    // ------------------------------ epilogue ------------------------------
    const int r  = lane >> 2;
    const int c2 = (lane & 3) * 2;

    if (MODE == 1) {
        #pragma unroll
        for (int mt = 0; mt < 2; mt++) {
            int m = m0 + wm * 32 + mt * 16 + r;
            #pragma unroll
            for (int nt = 0; nt < 4; nt++) {
                int e = n0 + wn * 32 + nt * 8 + c2;
                float2 bb = *(const float2*)&bias[e];
                float2 v0 = { acc[mt][nt][0] + bb.x, acc[mt][nt][1] + bb.y };
                float2 v1 = { acc[mt][nt][2] + bb.x, acc[mt][nt][3] + bb.y };
                *(float2*)&C[(size_t)m * DIMM + e]       = v0;
                *(float2*)&C[(size_t)(m + 8) * DIMM + e] = v1;
            }
        }
    } else {
        const int part = n0 >> 10;              // 0=q 1=k 2=v
        if (part < 2) {
            __nv_bfloat16* dh = part ? g_k_h : g_q_h;
            __nv_bfloat16* dl = part ? g_k_l : g_q_l;
            const float sc = part ? 1.0f : 0.125f;
            #pragma unroll
            for (int mt = 0; mt < 2; mt++) {
                int m = m0 + wm * 32 + mt * 16 + r;
                int bb_ = m >> 11, nloc = m & 2047;
                #pragma unroll
                for (int nt = 0; nt < 4; nt++) {
                    int eg = n0 + wn * 32 + nt * 8 + c2;
                    float2 bv = *(const float2*)&bias[eg];
                    int e = eg & 1023;
                    int h = e >> 6, d = e & 63;
                    size_t o = ((size_t)((bb_ * HEADS + h) * SEQ + nloc)) * HD + d;
                    uint32_t hh, ll;
                    split2((acc[mt][nt][0] + bv.x) * sc, (acc[mt][nt][1] + bv.y) * sc, hh, ll);
                    *(uint32_t*)&dh[o] = hh;
                    *(uint32_t*)&dl[o] = ll;
                    split2((acc[mt][nt][2] + bv.x) * sc, (acc[mt][nt][3] + bv.y) * sc, hh, ll);
                    *(uint32_t*)&dh[o + 8 * HD] = hh;
                    *(uint32_t*)&dl[o + 8 * HD] = ll;
                }
            }
        } else {
            // v: bounce fp32 via smem, transpose, split to g_vT hi/lo [d][n]
            float* Ds = smem_f;                  // [128][129]
            __syncthreads();
            #pragma unroll
            for (int mt = 0; mt < 2; mt++) {
                int ml = wm * 32 + mt * 16 + r;
                #pragma unroll
                for (int nt = 0; nt < 4; nt++) {
                    int el = wn * 32 + nt * 8 + c2;
                    float2 bv = *(const float2*)&bias[n0 + el];
                    Ds[ml * 129 + el]           = acc[mt][nt][0] + bv.x;
                    Ds[ml * 129 + el + 1]       = acc[mt][nt][1] + bv.y;
                    Ds[(ml + 8) * 129 + el]     = acc[mt][nt][2] + bv.x;
                    Ds[(ml + 8) * 129 + el + 1] = acc[mt][nt][3] + bv.y;
                }
            }
            __syncthreads();
            int e  = t >> 2;                     // d index within tile (0..127)
            int mh = (t & 3) * 32;               // n quarter
            int dg = (n0 & 1023) + e;
            int h = dg >> 6, d = dg & 63;
            int bb_ = m0 >> 11, nloc = m0 & 2047;
            size_t ob = ((size_t)((bb_ * HEADS + h) * HD + d)) * SEQ + nloc + mh;
            #pragma unroll 4
            for (int i = 0; i < 32; i += 4) {
                uint32_t h0, l0, h1, l1;
                split2(Ds[(mh + i) * 129 + e],     Ds[(mh + i + 1) * 129 + e], h0, l0);
                split2(Ds[(mh + i + 2) * 129 + e], Ds[(mh + i + 3) * 129 + e], h1, l1);
                uint2 vh = { h0, h1 }, vl = { l0, l1 };
                *(uint2*)&g_vT_h[ob + i] = vh;
                *(uint2*)&g_vT_l[ob + i] = vl;
            }
        }
    }
}

// ---------------------------------------------------------------------------
// Flash attention, 3xBF16, term-major. CTA = 128 q-rows (8 warps, m16/warp),
// 256 threads, j-tile 64. SMEM: Qh/Ql 16KB each; 2 stages x (Kh,Kl,Vh,Vl 8KB).
// 96KB, 1 CTA/SM but 2 warps/SMSP. Epilogue writes g_ao pre-split hi/lo.
// ---------------------------------------------------------------------------
#define F_SMEM (32768 + 2 * 32768)   // 96KB

__global__ __launch_bounds__(256, 1) void flash_kernel()
{
    extern __shared__ float fs[];
    const uint32_t base = smem_u32(fs);
    const uint32_t Qh = base, Ql = base + 16384;
    const uint32_t St = base + 32768;            // stages

    const int t = threadIdx.x, lane = t & 31, w = t >> 5;   // w 0..7
    const int bh = blockIdx.x, i0 = blockIdx.y;             // i0 0..15
    const int r = lane >> 2, q = lane & 3;

    // Q tile (once): 128 rows
    {
        const __nv_bfloat16* qh = g_q_h + ((size_t)bh * SEQ + i0 * 128) * HD;
        const __nv_bfloat16* ql = g_q_l + ((size_t)bh * SEQ + i0 * 128) * HD;
        #pragma unroll
        for (int i = 0; i < 4; i++) {
            int u = t + i * 256;                 // 0..1023
            int rr = u >> 3, c = u & 7;
            uint32_t sw = sw128((uint32_t)(rr * 128 + c * 16));
            cp16(Qh + sw, qh + (size_t)rr * HD + c * 8);
            cp16(Ql + sw, ql + (size_t)rr * HD + c * 8);
        }
        CP_COMMIT();
    }
    auto loadKV = [&](int j) {
        uint32_t S = St + (j & 1) * 32768;
        const __nv_bfloat16* kh = g_k_h  + ((size_t)bh * SEQ + j * 64) * HD;
        const __nv_bfloat16* kl = g_k_l  + ((size_t)bh * SEQ + j * 64) * HD;
        const __nv_bfloat16* vh = g_vT_h + (size_t)bh * HD * SEQ + j * 64;
        const __nv_bfloat16* vl = g_vT_l + (size_t)bh * HD * SEQ + j * 64;
        #pragma unroll
        for (int i = 0; i < 2; i++) {
            int u = t + i * 256;                 // 0..511
            int rr = u >> 3, c = u & 7;
            uint32_t sw = sw128((uint32_t)(rr * 128 + c * 16));
            cp16(S + sw,         kh + (size_t)rr * HD + c * 8);
            cp16(S + 8192 + sw,  kl + (size_t)rr * HD + c * 8);
            cp16(S + 16384 + sw, vh + (size_t)rr * SEQ + c * 8);
            cp16(S + 24576 + sw, vl + (size_t)rr * SEQ + c * 8);
        }
        CP_COMMIT();
    };
    loadKV(0);

    float oacc[8][4];
    #pragma unroll
    for (int d = 0; d < 8; d++)
        #pragma unroll
        for (int i = 0; i < 4; i++) oacc[d][i] = 0.0f;
    float mrow[2] = { -CUDART_INF_F, -CUDART_INF_F };
    float lrow[2] = { 0.0f, 0.0f };

    for (int j = 0; j < SEQ / 64; ++j) {
        if (j + 1 < SEQ / 64) { loadKV(j + 1); CP_WAIT(1); }
        else                  { CP_WAIT(0); }
        __syncthreads();
        const uint32_t sK = St + (j & 1) * 32768;
        const uint32_t sV = sK + 16384;

        // ---- S = Q K^T (scale folded into Q), 3xBF16, term-major ----
        float sacc[8][4];
        #pragma unroll
        for (int nt = 0; nt < 8; nt++)
            #pragma unroll
            for (int i = 0; i < 4; i++) sacc[nt][i] = 0.0f;

        #pragma unroll
        for (int cc = 0; cc < 4; ++cc) {        // k16 over d=64
            uint32_t ah[4], al[4];
            {
                int row = w * 16 + (lane & 15);
                uint32_t bc = cc * 32 + (lane >> 4) * 16;
                ldsm4(ah[0], ah[1], ah[2], ah[3], Qh + sw128((uint32_t)(row * 128) + bc));
                ldsm4(al[0], al[1], al[2], al[3], Ql + sw128((uint32_t)(row * 128) + bc));
            }
            uint32_t kbh[4][4], kbl[4][4];
            #pragma unroll
            for (int g = 0; g < 4; g++) {
                int row = g * 16 + (lane & 7) + ((lane & 16) ? 8 : 0);
                uint32_t bc = cc * 32 + ((lane & 8) ? 16 : 0);
                ldsm4(kbh[g][0], kbh[g][1], kbh[g][2], kbh[g][3],
                      sK + sw128((uint32_t)(row * 128) + bc));
                ldsm4(kbl[g][0], kbl[g][1], kbl[g][2], kbl[g][3],
                      sK + 8192 + sw128((uint32_t)(row * 128) + bc));
            }
            #pragma unroll
            for (int g = 0; g < 4; g++) {
                mma16(sacc[2*g],     ah, kbh[g]);
                mma16(sacc[2*g + 1], ah, kbh[g] + 2);
            }
            #pragma unroll
            for (int g = 0; g < 4; g++) {
                mma16(sacc[2*g],     al, kbh[g]);
                mma16(sacc[2*g + 1], al, kbh[g] + 2);
            }
            #pragma unroll
            for (int g = 0; g < 4; g++) {
                mma16(sacc[2*g],     ah, kbl[g]);
                mma16(sacc[2*g + 1], ah, kbl[g] + 2);
            }
        }

        // ---- online softmax ----
        #pragma unroll
        for (int rp = 0; rp < 2; rp++) {
            const int lo = rp * 2;
            float mx = -CUDART_INF_F;
            #pragma unroll
            for (int nt = 0; nt < 8; nt++)
                mx = fmaxf(mx, fmaxf(sacc[nt][lo], sacc[nt][lo + 1]));
            mx = fmaxf(mx, __shfl_xor_sync(0xffffffffu, mx, 1));
            mx = fmaxf(mx, __shfl_xor_sync(0xffffffffu, mx, 2));
            float mn = fmaxf(mrow[rp], mx);
            float corr = __expf(mrow[rp] - mn);
            mrow[rp] = mn;
            float sum = 0.0f;
            #pragma unroll
            for (int nt = 0; nt < 8; nt++) {
                float p0 = __expf(sacc[nt][lo] - mn);
                float p1 = __expf(sacc[nt][lo + 1] - mn);
                sacc[nt][lo] = p0; sacc[nt][lo + 1] = p1;
                sum += p0 + p1;
            }
            sum += __shfl_xor_sync(0xffffffffu, sum, 1);
            sum += __shfl_xor_sync(0xffffffffu, sum, 2);
            lrow[rp] = lrow[rp] * corr + sum;
            #pragma unroll
            for (int d = 0; d < 8; d++) {
                oacc[d][lo]     *= corr;
                oacc[d][lo + 1] *= corr;
            }
        }

        // ---- O += P V  (P split in-register; term-major) ----
        #pragma unroll
        for (int kc = 0; kc < 4; ++kc) {        // k16 over 64 keys
            uint32_t ph[4], pl[4];
            split2(sacc[2*kc][0],     sacc[2*kc][1],     ph[0], pl[0]);
            split2(sacc[2*kc][2],     sacc[2*kc][3],     ph[1], pl[1]);
            split2(sacc[2*kc + 1][0], sacc[2*kc + 1][1], ph[2], pl[2]);
            split2(sacc[2*kc + 1][2], sacc[2*kc + 1][3], ph[3], pl[3]);
            uint32_t vbh[4][4], vbl[4][4];
            #pragma unroll
            for (int g = 0; g < 4; g++) {
                int row = g * 16 + (lane & 7) + ((lane & 16) ? 8 : 0);
                uint32_t bc = kc * 32 + ((lane & 8) ? 16 : 0);
                ldsm4(vbh[g][0], vbh[g][1], vbh[g][2], vbh[g][3],
                      sV + sw128((uint32_t)(row * 128) + bc));
                ldsm4(vbl[g][0], vbl[g][1], vbl[g][2], vbl[g][3],
                      sV + 8192 + sw128((uint32_t)(row * 128) + bc));
            }
            #pragma unroll
            for (int g = 0; g < 4; g++) {
                mma16(oacc[2*g],     ph, vbh[g]);
                mma16(oacc[2*g + 1], ph, vbh[g] + 2);
            }
            #pragma unroll
            for (int g = 0; g < 4; g++) {
                mma16(oacc[2*g],     pl, vbh[g]);
                mma16(oacc[2*g + 1], pl, vbh[g] + 2);
            }
            #pragma unroll
            for (int g = 0; g < 4; g++) {
                mma16(oacc[2*g],     ph, vbl[g]);
                mma16(oacc[2*g + 1], ph, vbl[g] + 2);
            }
        }
        __syncthreads();
    }

    // ---- write O pre-split (bf16 hi/lo planes) ----
    const int bb = bh >> 4, h = bh & 15;
    #pragma unroll
    for (int rp = 0; rp < 2; rp++) {
        float inv = 1.0f / lrow[rp];
        int n = i0 * 128 + w * 16 + r + rp * 8;
        size_t ob = ((size_t)(bb * SEQ + n)) * DIMM + h * 64;
        #pragma unroll
        for (int d = 0; d < 8; d++) {
            uint32_t hh, ll;
            split2(oacc[d][rp * 2] * inv, oacc[d][rp * 2 + 1] * inv, hh, ll);
            *(uint32_t*)&g_ao_h[ob + d * 8 + q * 2] = hh;
            *(uint32_t*)&g_ao_l[ob + d * 8 + q * 2] = ll;
        }
    }
}

// ---------------------------------------------------------------------------
extern "C" void kernel_launch(void* const* d_in, const int* in_sizes, int n_in,
                              void* d_out, int out_size)
{
    const float* x     = (const float*)d_in[0];
    const float* W_qkv = (const float*)d_in[1];
    const float* b_qkv = (const float*)d_in[2];
    const float* W_out = (const float*)d_in[3];
    const float* b_out = (const float*)d_in[4];
    float* out = (float*)d_out;

    cudaFuncSetAttribute(gemm_tc<0>, cudaFuncAttributeMaxDynamicSharedMemorySize, GEMM_SMEM);
    cudaFuncSetAttribute(gemm_tc<1>, cudaFuncAttributeMaxDynamicSharedMemorySize, GEMM_SMEM);
    cudaFuncSetAttribute(flash_kernel, cudaFuncAttributeMaxDynamicSharedMemorySize, F_SMEM);

    __nv_bfloat16 *xh, *xl, *wqh, *wql, *woh, *wol;
    cudaGetSymbolAddress((void**)&xh,  g_x_h);  cudaGetSymbolAddress((void**)&xl,  g_x_l);
    cudaGetSymbolAddress((void**)&wqh, g_wq_h); cudaGetSymbolAddress((void**)&wql, g_wq_l);
    cudaGetSymbolAddress((void**)&woh, g_wo_h); cudaGetSymbolAddress((void**)&wol, g_wo_l);
    __nv_bfloat16 *aoh, *aol;
    cudaGetSymbolAddress((void**)&aoh, g_ao_h); cudaGetSymbolAddress((void**)&aol, g_ao_l);

    split_kernel<<<(MROWS*DIMM/4 + 255)/256, 256>>>(x,     xh,  xl,  MROWS*DIMM/4);
    split_kernel<<<(QKVN*DIMM/4 + 255)/256, 256>>>(W_qkv, wqh, wql, QKVN*DIMM/4);
    split_kernel<<<(DIMM*DIMM/4 + 255)/256, 256>>>(W_out, woh, wol, DIMM*DIMM/4);

    gemm_tc<0><<<dim3(QKVN/128, MROWS/128), 512, GEMM_SMEM>>>(xh, xl, wqh, wql, b_qkv, nullptr);
    flash_kernel<<<dim3(BH, SEQ/128), 256, F_SMEM>>>();
    gemm_tc<1><<<dim3(DIMM/128, MROWS/128), 512, GEMM_SMEM>>>(aoh, aol, woh, wol, b_out, out);
}

// round 13
// speedup vs baseline: 1.4754x; 1.4754x over previous
#include <cuda_runtime.h>
#include <cuda_fp16.h>
#include <cstdint>
#include <math_constants.h>

// Problem constants
#define BSZ   2
#define SEQ   2048
#define DIMM  1024
#define HEADS 16
#define HD    64
#define MROWS (BSZ*SEQ)      // 4096
#define QKVN  (3*DIMM)       // 3072
#define BH    (BSZ*HEADS)    // 32

// Scratch (device globals: allocation-free rule)
__device__ __half g_x_h [MROWS*DIMM], g_x_l [MROWS*DIMM];   // split x (A side)
__device__ __half g_wq_h[QKVN*DIMM];                        // W_qkv hi only (B side)
__device__ __half g_wo_h[DIMM*DIMM];                        // W_out hi only
__device__ __half g_q_h [BH*SEQ*HD],  g_q_l [BH*SEQ*HD];    // [bh][n][d], x1/8 (A side)
__device__ __half g_k_h [BH*SEQ*HD];                        // [bh][n][d] hi only (B side)
__device__ __half g_vT_h[BH*HD*SEQ];                        // [bh][d][n] hi only (B side)
__device__ __half g_ao_h[MROWS*DIMM], g_ao_l[MROWS*DIMM];   // [b*n][h*64+d] (A side)

// ---------------------------------------------------------------------------
// helpers
// ---------------------------------------------------------------------------
__device__ __forceinline__ uint32_t smem_u32(const void* p) {
    uint32_t a;
    asm("{ .reg .u64 t; cvta.to.shared.u64 t, %1; cvt.u32.u64 %0, t; }"
        : "=r"(a) : "l"(p));
    return a;
}
__device__ __forceinline__ void cp16(uint32_t dst, const void* src) {
    asm volatile("cp.async.cg.shared.global [%0], [%1], 16;"
                 :: "r"(dst), "l"(src) : "memory");
}
#define CP_COMMIT() asm volatile("cp.async.commit_group;" ::: "memory")
#define CP_WAIT(n)  asm volatile("cp.async.wait_group %0;" :: "n"(n) : "memory")

__device__ __forceinline__ void ldsm4(uint32_t& r0, uint32_t& r1, uint32_t& r2,
                                      uint32_t& r3, uint32_t a) {
    asm volatile("ldmatrix.sync.aligned.m8n8.x4.shared.b16 {%0,%1,%2,%3}, [%4];"
                 : "=r"(r0), "=r"(r1), "=r"(r2), "=r"(r3) : "r"(a));
}
// mma m16n8k16 fp16: D(f32) += A(f16) * B(f16)
__device__ __forceinline__ void mma16(float* c, const uint32_t* a, const uint32_t* b) {
    asm volatile(
        "mma.sync.aligned.m16n8k16.row.col.f32.f16.f16.f32 "
        "{%0,%1,%2,%3},{%4,%5,%6,%7},{%8,%9},{%0,%1,%2,%3};"
        : "+f"(c[0]), "+f"(c[1]), "+f"(c[2]), "+f"(c[3])
        : "r"(a[0]), "r"(a[1]), "r"(a[2]), "r"(a[3]), "r"(b[0]), "r"(b[1]));
}
__device__ __forceinline__ uint32_t sw128(uint32_t o) { return o ^ ((o >> 3) & 0x70); }
__device__ __forceinline__ uint32_t sw64 (uint32_t o) { return o ^ ((o >> 3) & 0x30); }

// pack two floats to f16x2: x0 -> lower 16 bits (k even), x1 -> upper
__device__ __forceinline__ uint32_t packh(float x0, float x1) {
    uint32_t d;
    asm("cvt.rn.f16x2.f32 %0, %1, %2;" : "=r"(d) : "f"(x1), "f"(x0));
    return d;
}
__device__ __forceinline__ void unpackh(uint32_t h, float& f0, float& f1) {
    asm("{ .reg .b16 lo, hi; mov.b32 {lo, hi}, %2; "
        "cvt.f32.f16 %0, lo; cvt.f32.f16 %1, hi; }"
        : "=f"(f0), "=f"(f1) : "r"(h));
}
// split pair: h = f16x2(hi parts), l = f16x2(residuals)
__device__ __forceinline__ void split2(float x0, float x1, uint32_t& h, uint32_t& l) {
    h = packh(x0, x1);
    float f0, f1;
    unpackh(h, f0, f1);
    l = packh(x0 - f0, x1 - f1);
}

// ---------------------------------------------------------------------------
// Pre-split kernels: fp32 -> f16 hi(+lo) planes (over float4)
// ---------------------------------------------------------------------------
__global__ void split_hl_kernel(const float* __restrict__ src,
                                __half* __restrict__ dh,
                                __half* __restrict__ dl, int n4)
{
    int i = blockIdx.x * blockDim.x + threadIdx.x;
    if (i >= n4) return;
    float4 v = ((const float4*)src)[i];
    uint32_t h0, l0, h1, l1;
    split2(v.x, v.y, h0, l0);
    split2(v.z, v.w, h1, l1);
    uint2 hh = { h0, h1 }, ll = { l0, l1 };
    ((uint2*)dh)[i] = hh;
    ((uint2*)dl)[i] = ll;
}
__global__ void split_h_kernel(const float* __restrict__ src,
                               __half* __restrict__ dh, int n4)
{
    int i = blockIdx.x * blockDim.x + threadIdx.x;
    if (i >= n4) return;
    float4 v = ((const float4*)src)[i];
    uint2 hh = { packh(v.x, v.y), packh(v.z, v.w) };
    ((uint2*)dh)[i] = hh;
}

// ---------------------------------------------------------------------------
// 2xFP16 GEMM: C[m,e] = sum_k (Ah+Al)[m,k] * Wh[e,k] + bias[e]
// 128x128 tile, K-tile 32, 4-stage cp.async, 512 threads (4x4 warps, 32x32).
// Stage: A [128 rows][hi 64B | lo 64B] sw128 (16KB) + B [128 rows][64B] sw64 (8KB).
// MODE 0: scatter f16 into g_q (hi/lo, x1/8) / g_k (hi) / g_vT (hi).
// MODE 1: C = out (fp32).
// ---------------------------------------------------------------------------
#define GSTG      24576
#define GSTAGES   4
#define GEMM_SMEM (GSTAGES * GSTG)        // 96KB (also reused as Ds 128x129 f32)

template<int MODE>
__global__ __launch_bounds__(512, 1) void gemm_tc(
    const __half* __restrict__ Ah, const __half* __restrict__ Al,
    const __half* __restrict__ Bh,
    const float* __restrict__ bias, float* __restrict__ C)
{
    extern __shared__ float smem_f[];
    const uint32_t base = smem_u32(smem_f);
    const int t = threadIdx.x, lane = t & 31, wid = t >> 5;   // wid 0..15
    const int wm = wid >> 2, wn = wid & 3;      // 4 x 4 warp grid, 32x32 tiles
    const int m0 = blockIdx.y * 128, n0 = blockIdx.x * 128;

    auto stage_load = [&](int kt) {
        uint32_t S = base + (kt & (GSTAGES - 1)) * GSTG;
        int r = t >> 2, c = t & 3;               // row 0..127, 16B col 0..3
        size_t ao = (size_t)(m0 + r) * DIMM + kt * 32 + c * 8;
        size_t bo = (size_t)(n0 + r) * DIMM + kt * 32 + c * 8;
        cp16(S + sw128((uint32_t)(r * 128 + c * 16)), Ah + ao);
        cp16(S + sw128((uint32_t)(r * 128 + 64 + c * 16)), Al + ao);
        cp16(S + 16384 + sw64((uint32_t)(r * 64 + c * 16)), Bh + bo);
        CP_COMMIT();
    };

    float acc[2][4][4];
    #pragma unroll
    for (int mt = 0; mt < 2; mt++)
        #pragma unroll
        for (int nt = 0; nt < 4; nt++)
            #pragma unroll
            for (int i = 0; i < 4; i++) acc[mt][nt][i] = 0.0f;

    stage_load(0);
    stage_load(1);
    stage_load(2);

    const int KT = DIMM / 32;   // 32
    for (int kt = 0; kt < KT; ++kt) {
        if (kt < KT - 2)       CP_WAIT(2);
        else if (kt == KT - 2) CP_WAIT(1);
        else                   CP_WAIT(0);
        __syncthreads();

        uint32_t sA = base + (kt & (GSTAGES - 1)) * GSTG, sB = sA + 16384;
        #pragma unroll
        for (int cc = 0; cc < 2; ++cc) {        // k16 chunks
            uint32_t ah[2][4], al[2][4];
            #pragma unroll
            for (int mt = 0; mt < 2; mt++) {
                int row = wm * 32 + mt * 16 + (lane & 15);
                uint32_t bc = cc * 32 + (lane >> 4) * 16;
                ldsm4(ah[mt][0], ah[mt][1], ah[mt][2], ah[mt][3],
                      sA + sw128((uint32_t)(row * 128) + bc));
                ldsm4(al[mt][0], al[mt][1], al[mt][2], al[mt][3],
                      sA + sw128((uint32_t)(row * 128) + 64 + bc));
            }
            uint32_t bh4[2][4];
            #pragma unroll
            for (int g = 0; g < 2; g++) {
                int row = wn * 32 + g * 16 + (lane & 7) + ((lane & 16) ? 8 : 0);
                uint32_t bc = cc * 32 + ((lane & 8) ? 16 : 0);
                ldsm4(bh4[g][0], bh4[g][1], bh4[g][2], bh4[g][3],
                      sB + sw64((uint32_t)(row * 64) + bc));
            }
            // term-major: hi pass over all 8 accs, then lo pass
            #pragma unroll
            for (int g = 0; g < 2; g++)
                #pragma unroll
                for (int mt = 0; mt < 2; mt++) {
                    mma16(acc[mt][2*g],     ah[mt], bh4[g]);
                    mma16(acc[mt][2*g + 1], ah[mt], bh4[g] + 2);
                }
            #pragma unroll
            for (int g = 0; g < 2; g++)
                #pragma unroll
                for (int mt = 0; mt < 2; mt++) {
                    mma16(acc[mt][2*g],     al[mt], bh4[g]);
                    mma16(acc[mt][2*g + 1], al[mt], bh4[g] + 2);
                }
        }
        if (kt + 3 < KT) stage_load(kt + 3);
    }

    // ------------------------------ epilogue ------------------------------
    const int r  = lane >> 2;
    const int c2 = (lane & 3) * 2;

    if (MODE == 1) {
        #pragma unroll
        for (int mt = 0; mt < 2; mt++) {
            int m = m0 + wm * 32 + mt * 16 + r;
            #pragma unroll
            for (int nt = 0; nt < 4; nt++) {
                int e = n0 + wn * 32 + nt * 8 + c2;
                float2 bb = *(const float2*)&bias[e];
                float2 v0 = { acc[mt][nt][0] + bb.x, acc[mt][nt][1] + bb.y };
                float2 v1 = { acc[mt][nt][2] + bb.x, acc[mt][nt][3] + bb.y };
                *(float2*)&C[(size_t)m * DIMM + e]       = v0;
                *(float2*)&C[(size_t)(m + 8) * DIMM + e] = v1;
            }
        }
    } else {
        const int part = n0 >> 10;              // 0=q 1=k 2=v
        if (part == 0) {
            #pragma unroll
            for (int mt = 0; mt < 2; mt++) {
                int m = m0 + wm * 32 + mt * 16 + r;
                int bb_ = m >> 11, nloc = m & 2047;
                #pragma unroll
                for (int nt = 0; nt < 4; nt++) {
                    int eg = n0 + wn * 32 + nt * 8 + c2;
                    float2 bv = *(const float2*)&bias[eg];
                    int e = eg & 1023;
                    int h = e >> 6, d = e & 63;
                    size_t o = ((size_t)((bb_ * HEADS + h) * SEQ + nloc)) * HD + d;
                    uint32_t hh, ll;
                    split2((acc[mt][nt][0] + bv.x) * 0.125f,
                           (acc[mt][nt][1] + bv.y) * 0.125f, hh, ll);
                    *(uint32_t*)&g_q_h[o] = hh;
                    *(uint32_t*)&g_q_l[o] = ll;
                    split2((acc[mt][nt][2] + bv.x) * 0.125f,
                           (acc[mt][nt][3] + bv.y) * 0.125f, hh, ll);
                    *(uint32_t*)&g_q_h[o + 8 * HD] = hh;
                    *(uint32_t*)&g_q_l[o + 8 * HD] = ll;
                }
            }
        } else if (part == 1) {
            #pragma unroll
            for (int mt = 0; mt < 2; mt++) {
                int m = m0 + wm * 32 + mt * 16 + r;
                int bb_ = m >> 11, nloc = m & 2047;
                #pragma unroll
                for (int nt = 0; nt < 4; nt++) {
                    int eg = n0 + wn * 32 + nt * 8 + c2;
                    float2 bv = *(const float2*)&bias[eg];
                    int e = eg & 1023;
                    int h = e >> 6, d = e & 63;
                    size_t o = ((size_t)((bb_ * HEADS + h) * SEQ + nloc)) * HD + d;
                    *(uint32_t*)&g_k_h[o] =
                        packh(acc[mt][nt][0] + bv.x, acc[mt][nt][1] + bv.y);
                    *(uint32_t*)&g_k_h[o + 8 * HD] =
                        packh(acc[mt][nt][2] + bv.x, acc[mt][nt][3] + bv.y);
                }
            }
        } else {
            // v: bounce fp32 via smem, transpose, write g_vT hi only [d][n]
            float* Ds = smem_f;                  // [128][129]
            __syncthreads();
            #pragma unroll
            for (int mt = 0; mt < 2; mt++) {
                int ml = wm * 32 + mt * 16 + r;
                #pragma unroll
                for (int nt = 0; nt < 4; nt++) {
                    int el = wn * 32 + nt * 8 + c2;
                    float2 bv = *(const float2*)&bias[n0 + el];
                    Ds[ml * 129 + el]           = acc[mt][nt][0] + bv.x;
                    Ds[ml * 129 + el + 1]       = acc[mt][nt][1] + bv.y;
                    Ds[(ml + 8) * 129 + el]     = acc[mt][nt][2] + bv.x;
                    Ds[(ml + 8) * 129 + el + 1] = acc[mt][nt][3] + bv.y;
                }
            }
            __syncthreads();
            int e  = t >> 2;                     // d index within tile (0..127)
            int mh = (t & 3) * 32;               // n quarter
            int dg = (n0 & 1023) + e;
            int h = dg >> 6, d = dg & 63;
            int bb_ = m0 >> 11, nloc = m0 & 2047;
            size_t ob = ((size_t)((bb_ * HEADS + h) * HD + d)) * SEQ + nloc + mh;
            #pragma unroll 4
            for (int i = 0; i < 32; i += 4) {
                uint2 vh = { packh(Ds[(mh + i) * 129 + e],     Ds[(mh + i + 1) * 129 + e]),
                             packh(Ds[(mh + i + 2) * 129 + e], Ds[(mh + i + 3) * 129 + e]) };
                *(uint2*)&g_vT_h[ob + i] = vh;
            }
        }
    }
}

// ---------------------------------------------------------------------------
// Flash attention, 2xFP16, term-major. CTA = 64 q-rows (4 warps), j-tile 64.
// SMEM: Qh 8KB + Ql 8KB; stages: (Kh 8KB + Vh 8KB) x2 = 32KB. 48KB total
// -> 3 CTAs/SM. Epilogue writes g_ao split hi/lo.
// ---------------------------------------------------------------------------
#define F_SMEM (16384 + 2 * 16384)   // 48KB

__global__ __launch_bounds__(128, 1) void flash_kernel()
{
    extern __shared__ float fs[];
    const uint32_t base = smem_u32(fs);
    const uint32_t Qh = base, Ql = base + 8192;
    const uint32_t St = base + 16384;            // stages

    const int t = threadIdx.x, lane = t & 31, w = t >> 5;
    const int bh = blockIdx.x, i0 = blockIdx.y;
    const int r = lane >> 2, q = lane & 3;

    // Q tile (once)
    {
        const __half* qh = g_q_h + ((size_t)bh * SEQ + i0 * 64) * HD;
        const __half* ql = g_q_l + ((size_t)bh * SEQ + i0 * 64) * HD;
        #pragma unroll
        for (int i = 0; i < 4; i++) {
            int u = t + i * 128;
            int rr = u >> 3, c = u & 7;
            uint32_t sw = sw128((uint32_t)(rr * 128 + c * 16));
            cp16(Qh + sw, qh + (size_t)rr * HD + c * 8);
            cp16(Ql + sw, ql + (size_t)rr * HD + c * 8);
        }
        CP_COMMIT();
    }
    auto loadKV = [&](int j) {
        uint32_t S = St + (j & 1) * 16384;
        const __half* kh = g_k_h  + ((size_t)bh * SEQ + j * 64) * HD;
        const __half* vh = g_vT_h + (size_t)bh * HD * SEQ + j * 64;
        #pragma unroll
        for (int i = 0; i < 4; i++) {
            int u = t + i * 128;
            int rr = u >> 3, c = u & 7;
            uint32_t sw = sw128((uint32_t)(rr * 128 + c * 16));
            cp16(S + sw,        kh + (size_t)rr * HD + c * 8);
            cp16(S + 8192 + sw, vh + (size_t)rr * SEQ + c * 8);
        }
        CP_COMMIT();
    };
    loadKV(0);

    float oacc[8][4];
    #pragma unroll
    for (int d = 0; d < 8; d++)
        #pragma unroll
        for (int i = 0; i < 4; i++) oacc[d][i] = 0.0f;
    float mrow[2] = { -CUDART_INF_F, -CUDART_INF_F };
    float lrow[2] = { 0.0f, 0.0f };

    for (int j = 0; j < SEQ / 64; ++j) {
        if (j + 1 < SEQ / 64) { loadKV(j + 1); CP_WAIT(1); }
        else                  { CP_WAIT(0); }
        __syncthreads();
        const uint32_t sK = St + (j & 1) * 16384;
        const uint32_t sV = sK + 8192;

        // ---- S = (Qh+Ql) Kh^T (scale folded into Q), term-major ----
        float sacc[8][4];
        #pragma unroll
        for (int nt = 0; nt < 8; nt++)
            #pragma unroll
            for (int i = 0; i < 4; i++) sacc[nt][i] = 0.0f;

        #pragma unroll
        for (int cc = 0; cc < 4; ++cc) {        // k16 over d=64
            uint32_t ah[4], al[4];
            {
                int row = w * 16 + (lane & 15);
                uint32_t bc = cc * 32 + (lane >> 4) * 16;
                ldsm4(ah[0], ah[1], ah[2], ah[3], Qh + sw128((uint32_t)(row * 128) + bc));
                ldsm4(al[0], al[1], al[2], al[3], Ql + sw128((uint32_t)(row * 128) + bc));
            }
            uint32_t kbh[4][4];
            #pragma unroll
            for (int g = 0; g < 4; g++) {
                int row = g * 16 + (lane & 7) + ((lane & 16) ? 8 : 0);
                uint32_t bc = cc * 32 + ((lane & 8) ? 16 : 0);
                ldsm4(kbh[g][0], kbh[g][1], kbh[g][2], kbh[g][3],
                      sK + sw128((uint32_t)(row * 128) + bc));
            }
            #pragma unroll
            for (int g = 0; g < 4; g++) {
                mma16(sacc[2*g],     ah, kbh[g]);
                mma16(sacc[2*g + 1], ah, kbh[g] + 2);
            }
            #pragma unroll
            for (int g = 0; g < 4; g++) {
                mma16(sacc[2*g],     al, kbh[g]);
                mma16(sacc[2*g + 1], al, kbh[g] + 2);
            }
        }

        // ---- online softmax ----
        #pragma unroll
        for (int rp = 0; rp < 2; rp++) {
            const int lo = rp * 2;
            float mx = -CUDART_INF_F;
            #pragma unroll
            for (int nt = 0; nt < 8; nt++)
                mx = fmaxf(mx, fmaxf(sacc[nt][lo], sacc[nt][lo + 1]));
            mx = fmaxf(mx, __shfl_xor_sync(0xffffffffu, mx, 1));
            mx = fmaxf(mx, __shfl_xor_sync(0xffffffffu, mx, 2));
            float mn = fmaxf(mrow[rp], mx);
            float corr = __expf(mrow[rp] - mn);
            mrow[rp] = mn;
            float sum = 0.0f;
            #pragma unroll
            for (int nt = 0; nt < 8; nt++) {
                float p0 = __expf(sacc[nt][lo] - mn);
                float p1 = __expf(sacc[nt][lo + 1] - mn);
                sacc[nt][lo] = p0; sacc[nt][lo + 1] = p1;
                sum += p0 + p1;
            }
            sum += __shfl_xor_sync(0xffffffffu, sum, 1);
            sum += __shfl_xor_sync(0xffffffffu, sum, 2);
            lrow[rp] = lrow[rp] * corr + sum;
            #pragma unroll
            for (int d = 0; d < 8; d++) {
                oacc[d][lo]     *= corr;
                oacc[d][lo + 1] *= corr;
            }
        }

        // ---- O += (Ph+Pl) Vh  (P split in-register; term-major) ----
        #pragma unroll
        for (int kc = 0; kc < 4; ++kc) {        // k16 over 64 keys
            uint32_t ph[4], pl[4];
            split2(sacc[2*kc][0],     sacc[2*kc][1],     ph[0], pl[0]);
            split2(sacc[2*kc][2],     sacc[2*kc][3],     ph[1], pl[1]);
            split2(sacc[2*kc + 1][0], sacc[2*kc + 1][1], ph[2], pl[2]);
            split2(sacc[2*kc + 1][2], sacc[2*kc + 1][3], ph[3], pl[3]);
            uint32_t vbh[4][4];
            #pragma unroll
            for (int g = 0; g < 4; g++) {
                int row = g * 16 + (lane & 7) + ((lane & 16) ? 8 : 0);
                uint32_t bc = kc * 32 + ((lane & 8) ? 16 : 0);
                ldsm4(vbh[g][0], vbh[g][1], vbh[g][2], vbh[g][3],
                      sV + sw128((uint32_t)(row * 128) + bc));
            }
            #pragma unroll
            for (int g = 0; g < 4; g++) {
                mma16(oacc[2*g],     ph, vbh[g]);
                mma16(oacc[2*g + 1], ph, vbh[g] + 2);
            }
            #pragma unroll
            for (int g = 0; g < 4; g++) {
                mma16(oacc[2*g],     pl, vbh[g]);
                mma16(oacc[2*g + 1], pl, vbh[g] + 2);
            }
        }
        __syncthreads();
    }

    // ---- write O pre-split (f16 hi/lo planes) ----
    const int bb = bh >> 4, h = bh & 15;
    #pragma unroll
    for (int rp = 0; rp < 2; rp++) {
        float inv = 1.0f / lrow[rp];
        int n = i0 * 64 + w * 16 + r + rp * 8;
        size_t ob = ((size_t)(bb * SEQ + n)) * DIMM + h * 64;
        #pragma unroll
        for (int d = 0; d < 8; d++) {
            uint32_t hh, ll;
            split2(oacc[d][rp * 2] * inv, oacc[d][rp * 2 + 1] * inv, hh, ll);
            *(uint32_t*)&g_ao_h[ob + d * 8 + q * 2] = hh;
            *(uint32_t*)&g_ao_l[ob + d * 8 + q * 2] = ll;
        }
    }
}

// ---------------------------------------------------------------------------
extern "C" void kernel_launch(void* const* d_in, const int* in_sizes, int n_in,
                              void* d_out, int out_size)
{
    const float* x     = (const float*)d_in[0];
    const float* W_qkv = (const float*)d_in[1];
    const float* b_qkv = (const float*)d_in[2];
    const float* W_out = (const float*)d_in[3];
    const float* b_out = (const float*)d_in[4];
    float* out = (float*)d_out;

    cudaFuncSetAttribute(gemm_tc<0>, cudaFuncAttributeMaxDynamicSharedMemorySize, GEMM_SMEM);
    cudaFuncSetAttribute(gemm_tc<1>, cudaFuncAttributeMaxDynamicSharedMemorySize, GEMM_SMEM);
    cudaFuncSetAttribute(flash_kernel, cudaFuncAttributeMaxDynamicSharedMemorySize, F_SMEM);

    __half *xh, *xl, *wqh, *woh, *aoh, *aol;
    cudaGetSymbolAddress((void**)&xh,  g_x_h);  cudaGetSymbolAddress((void**)&xl,  g_x_l);
    cudaGetSymbolAddress((void**)&wqh, g_wq_h);
    cudaGetSymbolAddress((void**)&woh, g_wo_h);
    cudaGetSymbolAddress((void**)&aoh, g_ao_h); cudaGetSymbolAddress((void**)&aol, g_ao_l);

    split_hl_kernel<<<(MROWS*DIMM/4 + 255)/256, 256>>>(x,     xh, xl, MROWS*DIMM/4);
    split_h_kernel <<<(QKVN*DIMM/4 + 255)/256, 256>>>(W_qkv, wqh,     QKVN*DIMM/4);
    split_h_kernel <<<(DIMM*DIMM/4 + 255)/256, 256>>>(W_out, woh,     DIMM*DIMM/4);

    gemm_tc<0><<<dim3(QKVN/128, MROWS/128), 512, GEMM_SMEM>>>(xh, xl, wqh, b_qkv, nullptr);
    flash_kernel<<<dim3(BH, SEQ/64), 128, F_SMEM>>>();
    gemm_tc<1><<<dim3(DIMM/128, MROWS/128), 512, GEMM_SMEM>>>(aoh, aol, woh, b_out, out);
}

// round 14
// speedup vs baseline: 1.7116x; 1.1601x over previous
#include <cuda_runtime.h>
#include <cuda_fp16.h>
#include <cstdint>
#include <math_constants.h>

// Problem constants
#define BSZ   2
#define SEQ   2048
#define DIMM  1024
#define HEADS 16
#define HD    64
#define MROWS (BSZ*SEQ)      // 4096
#define QKVN  (3*DIMM)       // 3072
#define BH    (BSZ*HEADS)    // 32

// Scratch (device globals: allocation-free rule)
__device__ __half g_x_h [MROWS*DIMM], g_x_l [MROWS*DIMM];   // split x (A side)
__device__ __half g_wq_h[QKVN*DIMM];                        // W_qkv hi only (B side)
__device__ __half g_wo_h[DIMM*DIMM];                        // W_out hi only
__device__ __half g_q_h [BH*SEQ*HD],  g_q_l [BH*SEQ*HD];    // [bh][n][d], x1/8 (A side)
__device__ __half g_k_h [BH*SEQ*HD];                        // [bh][n][d] hi only (B side)
__device__ __half g_vT_h[BH*HD*SEQ];                        // [bh][d][n] hi only (B side)
__device__ __half g_ao_h[MROWS*DIMM];                       // [b*n][h*64+d] hi only

// ---------------------------------------------------------------------------
// helpers
// ---------------------------------------------------------------------------
__device__ __forceinline__ uint32_t smem_u32(const void* p) {
    uint32_t a;
    asm("{ .reg .u64 t; cvta.to.shared.u64 t, %1; cvt.u32.u64 %0, t; }"
        : "=r"(a) : "l"(p));
    return a;
}
__device__ __forceinline__ void cp16(uint32_t dst, const void* src) {
    asm volatile("cp.async.cg.shared.global [%0], [%1], 16;"
                 :: "r"(dst), "l"(src) : "memory");
}
#define CP_COMMIT() asm volatile("cp.async.commit_group;" ::: "memory")
#define CP_WAIT(n)  asm volatile("cp.async.wait_group %0;" :: "n"(n) : "memory")

__device__ __forceinline__ void ldsm4(uint32_t& r0, uint32_t& r1, uint32_t& r2,
                                      uint32_t& r3, uint32_t a) {
    asm volatile("ldmatrix.sync.aligned.m8n8.x4.shared.b16 {%0,%1,%2,%3}, [%4];"
                 : "=r"(r0), "=r"(r1), "=r"(r2), "=r"(r3) : "r"(a));
}
// mma m16n8k16 fp16: D(f32) += A(f16) * B(f16)
__device__ __forceinline__ void mma16(float* c, const uint32_t* a, const uint32_t* b) {
    asm volatile(
        "mma.sync.aligned.m16n8k16.row.col.f32.f16.f16.f32 "
        "{%0,%1,%2,%3},{%4,%5,%6,%7},{%8,%9},{%0,%1,%2,%3};"
        : "+f"(c[0]), "+f"(c[1]), "+f"(c[2]), "+f"(c[3])
        : "r"(a[0]), "r"(a[1]), "r"(a[2]), "r"(a[3]), "r"(b[0]), "r"(b[1]));
}
__device__ __forceinline__ uint32_t sw128(uint32_t o) { return o ^ ((o >> 3) & 0x70); }
__device__ __forceinline__ uint32_t sw64 (uint32_t o) { return o ^ ((o >> 3) & 0x30); }

// pack two floats to f16x2: x0 -> lower 16 bits (k even), x1 -> upper
__device__ __forceinline__ uint32_t packh(float x0, float x1) {
    uint32_t d;
    asm("cvt.rn.f16x2.f32 %0, %1, %2;" : "=r"(d) : "f"(x1), "f"(x0));
    return d;
}
__device__ __forceinline__ void unpackh(uint32_t h, float& f0, float& f1) {
    asm("{ .reg .b16 lo, hi; mov.b32 {lo, hi}, %2; "
        "cvt.f32.f16 %0, lo; cvt.f32.f16 %1, hi; }"
        : "=f"(f0), "=f"(f1) : "r"(h));
}
// split pair: h = f16x2(hi parts), l = f16x2(residuals)
__device__ __forceinline__ void split2(float x0, float x1, uint32_t& h, uint32_t& l) {
    h = packh(x0, x1);
    float f0, f1;
    unpackh(h, f0, f1);
    l = packh(x0 - f0, x1 - f1);
}

// ---------------------------------------------------------------------------
// Pre-split kernels: fp32 -> f16 hi(+lo) planes (over float4)
// ---------------------------------------------------------------------------
__global__ void split_hl_kernel(const float* __restrict__ src,
                                __half* __restrict__ dh,
                                __half* __restrict__ dl, int n4)
{
    int i = blockIdx.x * blockDim.x + threadIdx.x;
    if (i >= n4) return;
    float4 v = ((const float4*)src)[i];
    uint32_t h0, l0, h1, l1;
    split2(v.x, v.y, h0, l0);
    split2(v.z, v.w, h1, l1);
    uint2 hh = { h0, h1 }, ll = { l0, l1 };
    ((uint2*)dh)[i] = hh;
    ((uint2*)dl)[i] = ll;
}
__global__ void split_h_kernel(const float* __restrict__ src,
                               __half* __restrict__ dh, int n4)
{
    int i = blockIdx.x * blockDim.x + threadIdx.x;
    if (i >= n4) return;
    float4 v = ((const float4*)src)[i];
    uint2 hh = { packh(v.x, v.y), packh(v.z, v.w) };
    ((uint2*)dh)[i] = hh;
}

// ---------------------------------------------------------------------------
// FP16 GEMM: C[m,e] = sum_k (Ah[+Al])[m,k] * Wh[e,k] + bias[e]
// ATERMS=2: A hi+lo compensation. ATERMS=1: plain fp16 A.
// 128x128 tile, K-tile 32, 4-stage cp.async, 512 threads (4x4 warps, 32x32).
// Stage: A [128 rows][hi 64B | lo 64B] sw128 (16KB) + B [128 rows][64B] sw64 (8KB).
// MODE 0: scatter f16 into g_q (hi/lo, x1/8) / g_k (hi) / g_vT (hi).
// MODE 1: C = out (fp32).
// ---------------------------------------------------------------------------
#define GSTG      24576
#define GSTAGES   4
#define GEMM_SMEM (GSTAGES * GSTG)        // 96KB (also reused as Ds 128x129 f32)

template<int MODE, int ATERMS>
__global__ __launch_bounds__(512, 1) void gemm_tc(
    const __half* __restrict__ Ah, const __half* __restrict__ Al,
    const __half* __restrict__ Bh,
    const float* __restrict__ bias, float* __restrict__ C)
{
    extern __shared__ float smem_f[];
    const uint32_t base = smem_u32(smem_f);
    const int t = threadIdx.x, lane = t & 31, wid = t >> 5;   // wid 0..15
    const int wm = wid >> 2, wn = wid & 3;      // 4 x 4 warp grid, 32x32 tiles
    const int m0 = blockIdx.y * 128, n0 = blockIdx.x * 128;

    auto stage_load = [&](int kt) {
        uint32_t S = base + (kt & (GSTAGES - 1)) * GSTG;
        int r = t >> 2, c = t & 3;               // row 0..127, 16B col 0..3
        size_t ao = (size_t)(m0 + r) * DIMM + kt * 32 + c * 8;
        size_t bo = (size_t)(n0 + r) * DIMM + kt * 32 + c * 8;
        cp16(S + sw128((uint32_t)(r * 128 + c * 16)), Ah + ao);
        if (ATERMS == 2)
            cp16(S + sw128((uint32_t)(r * 128 + 64 + c * 16)), Al + ao);
        cp16(S + 16384 + sw64((uint32_t)(r * 64 + c * 16)), Bh + bo);
        CP_COMMIT();
    };

    float acc[2][4][4];
    #pragma unroll
    for (int mt = 0; mt < 2; mt++)
        #pragma unroll
        for (int nt = 0; nt < 4; nt++)
            #pragma unroll
            for (int i = 0; i < 4; i++) acc[mt][nt][i] = 0.0f;

    stage_load(0);
    stage_load(1);
    stage_load(2);

    const int KT = DIMM / 32;   // 32
    for (int kt = 0; kt < KT; ++kt) {
        if (kt < KT - 2)       CP_WAIT(2);
        else if (kt == KT - 2) CP_WAIT(1);
        else                   CP_WAIT(0);
        __syncthreads();

        uint32_t sA = base + (kt & (GSTAGES - 1)) * GSTG, sB = sA + 16384;
        #pragma unroll
        for (int cc = 0; cc < 2; ++cc) {        // k16 chunks
            uint32_t ah[2][4], al[2][4];
            #pragma unroll
            for (int mt = 0; mt < 2; mt++) {
                int row = wm * 32 + mt * 16 + (lane & 15);
                uint32_t bc = cc * 32 + (lane >> 4) * 16;
                ldsm4(ah[mt][0], ah[mt][1], ah[mt][2], ah[mt][3],
                      sA + sw128((uint32_t)(row * 128) + bc));
                if (ATERMS == 2)
                    ldsm4(al[mt][0], al[mt][1], al[mt][2], al[mt][3],
                          sA + sw128((uint32_t)(row * 128) + 64 + bc));
            }
            uint32_t bh4[2][4];
            #pragma unroll
            for (int g = 0; g < 2; g++) {
                int row = wn * 32 + g * 16 + (lane & 7) + ((lane & 16) ? 8 : 0);
                uint32_t bc = cc * 32 + ((lane & 8) ? 16 : 0);
                ldsm4(bh4[g][0], bh4[g][1], bh4[g][2], bh4[g][3],
                      sB + sw64((uint32_t)(row * 64) + bc));
            }
            // term-major: hi pass over all 8 accs, then lo pass
            #pragma unroll
            for (int g = 0; g < 2; g++)
                #pragma unroll
                for (int mt = 0; mt < 2; mt++) {
                    mma16(acc[mt][2*g],     ah[mt], bh4[g]);
                    mma16(acc[mt][2*g + 1], ah[mt], bh4[g] + 2);
                }
            if (ATERMS == 2) {
                #pragma unroll
                for (int g = 0; g < 2; g++)
                    #pragma unroll
                    for (int mt = 0; mt < 2; mt++) {
                        mma16(acc[mt][2*g],     al[mt], bh4[g]);
                        mma16(acc[mt][2*g + 1], al[mt], bh4[g] + 2);
                    }
            }
        }
        if (kt + 3 < KT) stage_load(kt + 3);
    }

    // ------------------------------ epilogue ------------------------------
    const int r  = lane >> 2;
    const int c2 = (lane & 3) * 2;

    if (MODE == 1) {
        #pragma unroll
        for (int mt = 0; mt < 2; mt++) {
            int m = m0 + wm * 32 + mt * 16 + r;
            #pragma unroll
            for (int nt = 0; nt < 4; nt++) {
                int e = n0 + wn * 32 + nt * 8 + c2;
                float2 bb = *(const float2*)&bias[e];
                float2 v0 = { acc[mt][nt][0] + bb.x, acc[mt][nt][1] + bb.y };
                float2 v1 = { acc[mt][nt][2] + bb.x, acc[mt][nt][3] + bb.y };
                *(float2*)&C[(size_t)m * DIMM + e]       = v0;
                *(float2*)&C[(size_t)(m + 8) * DIMM + e] = v1;
            }
        }
    } else {
        const int part = n0 >> 10;              // 0=q 1=k 2=v
        if (part == 0) {
            #pragma unroll
            for (int mt = 0; mt < 2; mt++) {
                int m = m0 + wm * 32 + mt * 16 + r;
                int bb_ = m >> 11, nloc = m & 2047;
                #pragma unroll
                for (int nt = 0; nt < 4; nt++) {
                    int eg = n0 + wn * 32 + nt * 8 + c2;
                    float2 bv = *(const float2*)&bias[eg];
                    int e = eg & 1023;
                    int h = e >> 6, d = e & 63;
                    size_t o = ((size_t)((bb_ * HEADS + h) * SEQ + nloc)) * HD + d;
                    uint32_t hh, ll;
                    split2((acc[mt][nt][0] + bv.x) * 0.125f,
                           (acc[mt][nt][1] + bv.y) * 0.125f, hh, ll);
                    *(uint32_t*)&g_q_h[o] = hh;
                    *(uint32_t*)&g_q_l[o] = ll;
                    split2((acc[mt][nt][2] + bv.x) * 0.125f,
                           (acc[mt][nt][3] + bv.y) * 0.125f, hh, ll);
                    *(uint32_t*)&g_q_h[o + 8 * HD] = hh;
                    *(uint32_t*)&g_q_l[o + 8 * HD] = ll;
                }
            }
        } else if (part == 1) {
            #pragma unroll
            for (int mt = 0; mt < 2; mt++) {
                int m = m0 + wm * 32 + mt * 16 + r;
                int bb_ = m >> 11, nloc = m & 2047;
                #pragma unroll
                for (int nt = 0; nt < 4; nt++) {
                    int eg = n0 + wn * 32 + nt * 8 + c2;
                    float2 bv = *(const float2*)&bias[eg];
                    int e = eg & 1023;
                    int h = e >> 6, d = e & 63;
                    size_t o = ((size_t)((bb_ * HEADS + h) * SEQ + nloc)) * HD + d;
                    *(uint32_t*)&g_k_h[o] =
                        packh(acc[mt][nt][0] + bv.x, acc[mt][nt][1] + bv.y);
                    *(uint32_t*)&g_k_h[o + 8 * HD] =
                        packh(acc[mt][nt][2] + bv.x, acc[mt][nt][3] + bv.y);
                }
            }
        } else {
            // v: bounce fp32 via smem, transpose, write g_vT hi only [d][n]
            float* Ds = smem_f;                  // [128][129]
            __syncthreads();
            #pragma unroll
            for (int mt = 0; mt < 2; mt++) {
                int ml = wm * 32 + mt * 16 + r;
                #pragma unroll
                for (int nt = 0; nt < 4; nt++) {
                    int el = wn * 32 + nt * 8 + c2;
                    float2 bv = *(const float2*)&bias[n0 + el];
                    Ds[ml * 129 + el]           = acc[mt][nt][0] + bv.x;
                    Ds[ml * 129 + el + 1]       = acc[mt][nt][1] + bv.y;
                    Ds[(ml + 8) * 129 + el]     = acc[mt][nt][2] + bv.x;
                    Ds[(ml + 8) * 129 + el + 1] = acc[mt][nt][3] + bv.y;
                }
            }
            __syncthreads();
            int e  = t >> 2;                     // d index within tile (0..127)
            int mh = (t & 3) * 32;               // n quarter
            int dg = (n0 & 1023) + e;
            int h = dg >> 6, d = dg & 63;
            int bb_ = m0 >> 11, nloc = m0 & 2047;
            size_t ob = ((size_t)((bb_ * HEADS + h) * HD + d)) * SEQ + nloc + mh;
            #pragma unroll 4
            for (int i = 0; i < 32; i += 4) {
                uint2 vh = { packh(Ds[(mh + i) * 129 + e],     Ds[(mh + i + 1) * 129 + e]),
                             packh(Ds[(mh + i + 2) * 129 + e], Ds[(mh + i + 3) * 129 + e]) };
                *(uint2*)&g_vT_h[ob + i] = vh;
            }
        }
    }
}

// ---------------------------------------------------------------------------
// Flash attention: QK 2-term fp16, PV 1-term (P in [0,1], fp16-exact enough).
// CTA = 64 q-rows (4 warps), j-tile 64. SMEM: Qh+Ql 16KB; (Kh+Vh 16KB) x2.
// 48KB total -> 3 CTAs/SM. Epilogue writes g_ao hi only.
// ---------------------------------------------------------------------------
#define F_SMEM (16384 + 2 * 16384)   // 48KB

__global__ __launch_bounds__(128, 1) void flash_kernel()
{
    extern __shared__ float fs[];
    const uint32_t base = smem_u32(fs);
    const uint32_t Qh = base, Ql = base + 8192;
    const uint32_t St = base + 16384;            // stages

    const int t = threadIdx.x, lane = t & 31, w = t >> 5;
    const int bh = blockIdx.x, i0 = blockIdx.y;
    const int r = lane >> 2, q = lane & 3;

    // Q tile (once)
    {
        const __half* qh = g_q_h + ((size_t)bh * SEQ + i0 * 64) * HD;
        const __half* ql = g_q_l + ((size_t)bh * SEQ + i0 * 64) * HD;
        #pragma unroll
        for (int i = 0; i < 4; i++) {
            int u = t + i * 128;
            int rr = u >> 3, c = u & 7;
            uint32_t sw = sw128((uint32_t)(rr * 128 + c * 16));
            cp16(Qh + sw, qh + (size_t)rr * HD + c * 8);
            cp16(Ql + sw, ql + (size_t)rr * HD + c * 8);
        }
        CP_COMMIT();
    }
    auto loadKV = [&](int j) {
        uint32_t S = St + (j & 1) * 16384;
        const __half* kh = g_k_h  + ((size_t)bh * SEQ + j * 64) * HD;
        const __half* vh = g_vT_h + (size_t)bh * HD * SEQ + j * 64;
        #pragma unroll
        for (int i = 0; i < 4; i++) {
            int u = t + i * 128;
            int rr = u >> 3, c = u & 7;
            uint32_t sw = sw128((uint32_t)(rr * 128 + c * 16));
            cp16(S + sw,        kh + (size_t)rr * HD + c * 8);
            cp16(S + 8192 + sw, vh + (size_t)rr * SEQ + c * 8);
        }
        CP_COMMIT();
    };
    loadKV(0);

    float oacc[8][4];
    #pragma unroll
    for (int d = 0; d < 8; d++)
        #pragma unroll
        for (int i = 0; i < 4; i++) oacc[d][i] = 0.0f;
    float mrow[2] = { -CUDART_INF_F, -CUDART_INF_F };
    float lrow[2] = { 0.0f, 0.0f };

    for (int j = 0; j < SEQ / 64; ++j) {
        if (j + 1 < SEQ / 64) { loadKV(j + 1); CP_WAIT(1); }
        else                  { CP_WAIT(0); }
        __syncthreads();
        const uint32_t sK = St + (j & 1) * 16384;
        const uint32_t sV = sK + 8192;

        // ---- S = (Qh+Ql) Kh^T (scale folded into Q), term-major ----
        float sacc[8][4];
        #pragma unroll
        for (int nt = 0; nt < 8; nt++)
            #pragma unroll
            for (int i = 0; i < 4; i++) sacc[nt][i] = 0.0f;

        #pragma unroll
        for (int cc = 0; cc < 4; ++cc) {        // k16 over d=64
            uint32_t ah[4], al[4];
            {
                int row = w * 16 + (lane & 15);
                uint32_t bc = cc * 32 + (lane >> 4) * 16;
                ldsm4(ah[0], ah[1], ah[2], ah[3], Qh + sw128((uint32_t)(row * 128) + bc));
                ldsm4(al[0], al[1], al[2], al[3], Ql + sw128((uint32_t)(row * 128) + bc));
            }
            uint32_t kbh[4][4];
            #pragma unroll
            for (int g = 0; g < 4; g++) {
                int row = g * 16 + (lane & 7) + ((lane & 16) ? 8 : 0);
                uint32_t bc = cc * 32 + ((lane & 8) ? 16 : 0);
                ldsm4(kbh[g][0], kbh[g][1], kbh[g][2], kbh[g][3],
                      sK + sw128((uint32_t)(row * 128) + bc));
            }
            #pragma unroll
            for (int g = 0; g < 4; g++) {
                mma16(sacc[2*g],     ah, kbh[g]);
                mma16(sacc[2*g + 1], ah, kbh[g] + 2);
            }
            #pragma unroll
            for (int g = 0; g < 4; g++) {
                mma16(sacc[2*g],     al, kbh[g]);
                mma16(sacc[2*g + 1], al, kbh[g] + 2);
            }
        }

        // ---- online softmax ----
        #pragma unroll
        for (int rp = 0; rp < 2; rp++) {
            const int lo = rp * 2;
            float mx = -CUDART_INF_F;
            #pragma unroll
            for (int nt = 0; nt < 8; nt++)
                mx = fmaxf(mx, fmaxf(sacc[nt][lo], sacc[nt][lo + 1]));
            mx = fmaxf(mx, __shfl_xor_sync(0xffffffffu, mx, 1));
            mx = fmaxf(mx, __shfl_xor_sync(0xffffffffu, mx, 2));
            float mn = fmaxf(mrow[rp], mx);
            float corr = __expf(mrow[rp] - mn);
            mrow[rp] = mn;
            float sum = 0.0f;
            #pragma unroll
            for (int nt = 0; nt < 8; nt++) {
                float p0 = __expf(sacc[nt][lo] - mn);
                float p1 = __expf(sacc[nt][lo + 1] - mn);
                sacc[nt][lo] = p0; sacc[nt][lo + 1] = p1;
                sum += p0 + p1;
            }
            sum += __shfl_xor_sync(0xffffffffu, sum, 1);
            sum += __shfl_xor_sync(0xffffffffu, sum, 2);
            lrow[rp] = lrow[rp] * corr + sum;
            #pragma unroll
            for (int d = 0; d < 8; d++) {
                oacc[d][lo]     *= corr;
                oacc[d][lo + 1] *= corr;
            }
        }

        // ---- O += P Vh  (P 1-term fp16; term-major over 8 accs) ----
        #pragma unroll
        for (int kc = 0; kc < 4; ++kc) {        // k16 over 64 keys
            uint32_t ph[4];
            ph[0] = packh(sacc[2*kc][0],     sacc[2*kc][1]);
            ph[1] = packh(sacc[2*kc][2],     sacc[2*kc][3]);
            ph[2] = packh(sacc[2*kc + 1][0], sacc[2*kc + 1][1]);
            ph[3] = packh(sacc[2*kc + 1][2], sacc[2*kc + 1][3]);
            uint32_t vbh[4][4];
            #pragma unroll
            for (int g = 0; g < 4; g++) {
                int row = g * 16 + (lane & 7) + ((lane & 16) ? 8 : 0);
                uint32_t bc = kc * 32 + ((lane & 8) ? 16 : 0);
                ldsm4(vbh[g][0], vbh[g][1], vbh[g][2], vbh[g][3],
                      sV + sw128((uint32_t)(row * 128) + bc));
            }
            #pragma unroll
            for (int g = 0; g < 4; g++) {
                mma16(oacc[2*g],     ph, vbh[g]);
                mma16(oacc[2*g + 1], ph, vbh[g] + 2);
            }
        }
        __syncthreads();
    }

    // ---- write O (f16 hi only) ----
    const int bb = bh >> 4, h = bh & 15;
    #pragma unroll
    for (int rp = 0; rp < 2; rp++) {
        float inv = 1.0f / lrow[rp];
        int n = i0 * 64 + w * 16 + r + rp * 8;
        size_t ob = ((size_t)(bb * SEQ + n)) * DIMM + h * 64;
        #pragma unroll
        for (int d = 0; d < 8; d++) {
            *(uint32_t*)&g_ao_h[ob + d * 8 + q * 2] =
                packh(oacc[d][rp * 2] * inv, oacc[d][rp * 2 + 1] * inv);
        }
    }
}

// ---------------------------------------------------------------------------
extern "C" void kernel_launch(void* const* d_in, const int* in_sizes, int n_in,
                              void* d_out, int out_size)
{
    const float* x     = (const float*)d_in[0];
    const float* W_qkv = (const float*)d_in[1];
    const float* b_qkv = (const float*)d_in[2];
    const float* W_out = (const float*)d_in[3];
    const float* b_out = (const float*)d_in[4];
    float* out = (float*)d_out;

    cudaFuncSetAttribute((const void*)gemm_tc<0,2>, cudaFuncAttributeMaxDynamicSharedMemorySize, GEMM_SMEM);
    cudaFuncSetAttribute((const void*)gemm_tc<1,1>, cudaFuncAttributeMaxDynamicSharedMemorySize, GEMM_SMEM);
    cudaFuncSetAttribute(flash_kernel, cudaFuncAttributeMaxDynamicSharedMemorySize, F_SMEM);

    __half *xh, *xl, *wqh, *woh, *aoh;
    cudaGetSymbolAddress((void**)&xh,  g_x_h);  cudaGetSymbolAddress((void**)&xl,  g_x_l);
    cudaGetSymbolAddress((void**)&wqh, g_wq_h);
    cudaGetSymbolAddress((void**)&woh, g_wo_h);
    cudaGetSymbolAddress((void**)&aoh, g_ao_h);

    split_hl_kernel<<<(MROWS*DIMM/4 + 255)/256, 256>>>(x,     xh, xl, MROWS*DIMM/4);
    split_h_kernel <<<(QKVN*DIMM/4 + 255)/256, 256>>>(W_qkv, wqh,     QKVN*DIMM/4);
    split_h_kernel <<<(DIMM*DIMM/4 + 255)/256, 256>>>(W_out, woh,     DIMM*DIMM/4);

    gemm_tc<0,2><<<dim3(QKVN/128, MROWS/128), 512, GEMM_SMEM>>>(xh, xl, wqh, b_qkv, nullptr);
    flash_kernel<<<dim3(BH, SEQ/64), 128, F_SMEM>>>();
    gemm_tc<1,1><<<dim3(DIMM/128, MROWS/128), 512, GEMM_SMEM>>>(aoh, nullptr, woh, b_out, out);
}

// round 15
// speedup vs baseline: 1.8893x; 1.1039x over previous
#include <cuda_runtime.h>
#include <cuda_fp16.h>
#include <cstdint>
#include <math_constants.h>

// Problem constants
#define BSZ   2
#define SEQ   2048
#define DIMM  1024
#define HEADS 16
#define HD    64
#define MROWS (BSZ*SEQ)      // 4096
#define QKVN  (3*DIMM)       // 3072
#define BH    (BSZ*HEADS)    // 32

// Scratch (device globals: allocation-free rule)
__device__ __half g_x_h [MROWS*DIMM], g_x_l [MROWS*DIMM];   // split x (A side)
__device__ __half g_wq_h[QKVN*DIMM];                        // W_qkv hi only (B side)
__device__ __half g_wo_h[DIMM*DIMM];                        // W_out hi only
__device__ __half g_q_h [BH*SEQ*HD],  g_q_l [BH*SEQ*HD];    // [bh][n][d], x1/8 (A side)
__device__ __half g_k_h [BH*SEQ*HD];                        // [bh][n][d] hi only (B side)
__device__ __half g_vT_h[BH*HD*SEQ];                        // [bh][d][n] hi only (B side)
__device__ __half g_ao_h[MROWS*DIMM];                       // [b*n][h*64+d] hi only

// ---------------------------------------------------------------------------
// helpers
// ---------------------------------------------------------------------------
__device__ __forceinline__ uint32_t smem_u32(const void* p) {
    uint32_t a;
    asm("{ .reg .u64 t; cvta.to.shared.u64 t, %1; cvt.u32.u64 %0, t; }"
        : "=r"(a) : "l"(p));
    return a;
}
__device__ __forceinline__ void cp16(uint32_t dst, const void* src) {
    asm volatile("cp.async.cg.shared.global [%0], [%1], 16;"
                 :: "r"(dst), "l"(src) : "memory");
}
#define CP_COMMIT() asm volatile("cp.async.commit_group;" ::: "memory")
#define CP_WAIT(n)  asm volatile("cp.async.wait_group %0;" :: "n"(n) : "memory")

__device__ __forceinline__ void ldsm4(uint32_t& r0, uint32_t& r1, uint32_t& r2,
                                      uint32_t& r3, uint32_t a) {
    asm volatile("ldmatrix.sync.aligned.m8n8.x4.shared.b16 {%0,%1,%2,%3}, [%4];"
                 : "=r"(r0), "=r"(r1), "=r"(r2), "=r"(r3) : "r"(a));
}
// mma m16n8k16 fp16: D(f32) += A(f16) * B(f16)
__device__ __forceinline__ void mma16(float* c, const uint32_t* a, const uint32_t* b) {
    asm volatile(
        "mma.sync.aligned.m16n8k16.row.col.f32.f16.f16.f32 "
        "{%0,%1,%2,%3},{%4,%5,%6,%7},{%8,%9},{%0,%1,%2,%3};"
        : "+f"(c[0]), "+f"(c[1]), "+f"(c[2]), "+f"(c[3])
        : "r"(a[0]), "r"(a[1]), "r"(a[2]), "r"(a[3]), "r"(b[0]), "r"(b[1]));
}
__device__ __forceinline__ uint32_t sw128(uint32_t o) { return o ^ ((o >> 3) & 0x70); }
__device__ __forceinline__ uint32_t sw64 (uint32_t o) { return o ^ ((o >> 3) & 0x30); }

// pack two floats to f16x2: x0 -> lower 16 bits (k even), x1 -> upper
__device__ __forceinline__ uint32_t packh(float x0, float x1) {
    uint32_t d;
    asm("cvt.rn.f16x2.f32 %0, %1, %2;" : "=r"(d) : "f"(x1), "f"(x0));
    return d;
}
__device__ __forceinline__ void unpackh(uint32_t h, float& f0, float& f1) {
    asm("{ .reg .b16 lo, hi; mov.b32 {lo, hi}, %2; "
        "cvt.f32.f16 %0, lo; cvt.f32.f16 %1, hi; }"
        : "=f"(f0), "=f"(f1) : "r"(h));
}
// split pair: h = f16x2(hi parts), l = f16x2(residuals)
__device__ __forceinline__ void split2(float x0, float x1, uint32_t& h, uint32_t& l) {
    h = packh(x0, x1);
    float f0, f1;
    unpackh(h, f0, f1);
    l = packh(x0 - f0, x1 - f1);
}

// ---------------------------------------------------------------------------
// Pre-split kernels: fp32 -> f16 hi(+lo) planes (over float4)
// ---------------------------------------------------------------------------
__global__ void split_hl_kernel(const float* __restrict__ src,
                                __half* __restrict__ dh,
                                __half* __restrict__ dl, int n4)
{
    int i = blockIdx.x * blockDim.x + threadIdx.x;
    if (i >= n4) return;
    float4 v = ((const float4*)src)[i];
    uint32_t h0, l0, h1, l1;
    split2(v.x, v.y, h0, l0);
    split2(v.z, v.w, h1, l1);
    uint2 hh = { h0, h1 }, ll = { l0, l1 };
    ((uint2*)dh)[i] = hh;
    ((uint2*)dl)[i] = ll;
}
__global__ void split_h_kernel(const float* __restrict__ src,
                               __half* __restrict__ dh, int n4)
{
    int i = blockIdx.x * blockDim.x + threadIdx.x;
    if (i >= n4) return;
    float4 v = ((const float4*)src)[i];
    uint2 hh = { packh(v.x, v.y), packh(v.z, v.w) };
    ((uint2*)dh)[i] = hh;
}

// ---------------------------------------------------------------------------
// FP16 GEMM: C[m,e] = sum_k (Ah[+Al])[m,k] * Wh[e,k] + bias[e]
// ATERMS=2: A hi+lo compensation. ATERMS=1: plain fp16 A.
// nbase: global column offset of this launch's tile grid (for split-precision
// launches over disjoint column ranges).
// 128x128 tile, K-tile 32, 4-stage cp.async, 512 threads (4x4 warps, 32x32).
// MODE 0: scatter f16 into g_q (hi/lo, x1/8) / g_k (hi) / g_vT (hi).
// MODE 1: C = out (fp32).
// ---------------------------------------------------------------------------
#define GSTG      24576
#define GSTAGES   4
#define GEMM_SMEM (GSTAGES * GSTG)        // 96KB (also reused as Ds 128x129 f32)

template<int MODE, int ATERMS>
__global__ __launch_bounds__(512, 1) void gemm_tc(
    const __half* __restrict__ Ah, const __half* __restrict__ Al,
    const __half* __restrict__ Bh,
    const float* __restrict__ bias, float* __restrict__ C, int nbase)
{
    extern __shared__ float smem_f[];
    const uint32_t base = smem_u32(smem_f);
    const int t = threadIdx.x, lane = t & 31, wid = t >> 5;   // wid 0..15
    const int wm = wid >> 2, wn = wid & 3;      // 4 x 4 warp grid, 32x32 tiles
    const int m0 = blockIdx.y * 128, n0 = nbase + blockIdx.x * 128;

    auto stage_load = [&](int kt) {
        uint32_t S = base + (kt & (GSTAGES - 1)) * GSTG;
        int r = t >> 2, c = t & 3;               // row 0..127, 16B col 0..3
        size_t ao = (size_t)(m0 + r) * DIMM + kt * 32 + c * 8;
        size_t bo = (size_t)(n0 + r) * DIMM + kt * 32 + c * 8;
        cp16(S + sw128((uint32_t)(r * 128 + c * 16)), Ah + ao);
        if (ATERMS == 2)
            cp16(S + sw128((uint32_t)(r * 128 + 64 + c * 16)), Al + ao);
        cp16(S + 16384 + sw64((uint32_t)(r * 64 + c * 16)), Bh + bo);
        CP_COMMIT();
    };

    float acc[2][4][4];
    #pragma unroll
    for (int mt = 0; mt < 2; mt++)
        #pragma unroll
        for (int nt = 0; nt < 4; nt++)
            #pragma unroll
            for (int i = 0; i < 4; i++) acc[mt][nt][i] = 0.0f;

    stage_load(0);
    stage_load(1);
    stage_load(2);

    const int KT = DIMM / 32;   // 32
    for (int kt = 0; kt < KT; ++kt) {
        if (kt < KT - 2)       CP_WAIT(2);
        else if (kt == KT - 2) CP_WAIT(1);
        else                   CP_WAIT(0);
        __syncthreads();

        uint32_t sA = base + (kt & (GSTAGES - 1)) * GSTG, sB = sA + 16384;
        #pragma unroll
        for (int cc = 0; cc < 2; ++cc) {        // k16 chunks
            uint32_t ah[2][4], al[2][4];
            #pragma unroll
            for (int mt = 0; mt < 2; mt++) {
                int row = wm * 32 + mt * 16 + (lane & 15);
                uint32_t bc = cc * 32 + (lane >> 4) * 16;
                ldsm4(ah[mt][0], ah[mt][1], ah[mt][2], ah[mt][3],
                      sA + sw128((uint32_t)(row * 128) + bc));
                if (ATERMS == 2)
                    ldsm4(al[mt][0], al[mt][1], al[mt][2], al[mt][3],
                          sA + sw128((uint32_t)(row * 128) + 64 + bc));
            }
            uint32_t bh4[2][4];
            #pragma unroll
            for (int g = 0; g < 2; g++) {
                int row = wn * 32 + g * 16 + (lane & 7) + ((lane & 16) ? 8 : 0);
                uint32_t bc = cc * 32 + ((lane & 8) ? 16 : 0);
                ldsm4(bh4[g][0], bh4[g][1], bh4[g][2], bh4[g][3],
                      sB + sw64((uint32_t)(row * 64) + bc));
            }
            // term-major: hi pass over all 8 accs, then lo pass
            #pragma unroll
            for (int g = 0; g < 2; g++)
                #pragma unroll
                for (int mt = 0; mt < 2; mt++) {
                    mma16(acc[mt][2*g],     ah[mt], bh4[g]);
                    mma16(acc[mt][2*g + 1], ah[mt], bh4[g] + 2);
                }
            if (ATERMS == 2) {
                #pragma unroll
                for (int g = 0; g < 2; g++)
                    #pragma unroll
                    for (int mt = 0; mt < 2; mt++) {
                        mma16(acc[mt][2*g],     al[mt], bh4[g]);
                        mma16(acc[mt][2*g + 1], al[mt], bh4[g] + 2);
                    }
            }
        }
        if (kt + 3 < KT) stage_load(kt + 3);
    }

    // ------------------------------ epilogue ------------------------------
    const int r  = lane >> 2;
    const int c2 = (lane & 3) * 2;

    if (MODE == 1) {
        #pragma unroll
        for (int mt = 0; mt < 2; mt++) {
            int m = m0 + wm * 32 + mt * 16 + r;
            #pragma unroll
            for (int nt = 0; nt < 4; nt++) {
                int e = n0 + wn * 32 + nt * 8 + c2;
                float2 bb = *(const float2*)&bias[e];
                float2 v0 = { acc[mt][nt][0] + bb.x, acc[mt][nt][1] + bb.y };
                float2 v1 = { acc[mt][nt][2] + bb.x, acc[mt][nt][3] + bb.y };
                *(float2*)&C[(size_t)m * DIMM + e]       = v0;
                *(float2*)&C[(size_t)(m + 8) * DIMM + e] = v1;
            }
        }
    } else {
        const int part = n0 >> 10;              // 0=q 1=k 2=v
        if (part == 0) {
            #pragma unroll
            for (int mt = 0; mt < 2; mt++) {
                int m = m0 + wm * 32 + mt * 16 + r;
                int bb_ = m >> 11, nloc = m & 2047;
                #pragma unroll
                for (int nt = 0; nt < 4; nt++) {
                    int eg = n0 + wn * 32 + nt * 8 + c2;
                    float2 bv = *(const float2*)&bias[eg];
                    int e = eg & 1023;
                    int h = e >> 6, d = e & 63;
                    size_t o = ((size_t)((bb_ * HEADS + h) * SEQ + nloc)) * HD + d;
                    uint32_t hh, ll;
                    split2((acc[mt][nt][0] + bv.x) * 0.125f,
                           (acc[mt][nt][1] + bv.y) * 0.125f, hh, ll);
                    *(uint32_t*)&g_q_h[o] = hh;
                    *(uint32_t*)&g_q_l[o] = ll;
                    split2((acc[mt][nt][2] + bv.x) * 0.125f,
                           (acc[mt][nt][3] + bv.y) * 0.125f, hh, ll);
                    *(uint32_t*)&g_q_h[o + 8 * HD] = hh;
                    *(uint32_t*)&g_q_l[o + 8 * HD] = ll;
                }
            }
        } else if (part == 1) {
            #pragma unroll
            for (int mt = 0; mt < 2; mt++) {
                int m = m0 + wm * 32 + mt * 16 + r;
                int bb_ = m >> 11, nloc = m & 2047;
                #pragma unroll
                for (int nt = 0; nt < 4; nt++) {
                    int eg = n0 + wn * 32 + nt * 8 + c2;
                    float2 bv = *(const float2*)&bias[eg];
                    int e = eg & 1023;
                    int h = e >> 6, d = e & 63;
                    size_t o = ((size_t)((bb_ * HEADS + h) * SEQ + nloc)) * HD + d;
                    *(uint32_t*)&g_k_h[o] =
                        packh(acc[mt][nt][0] + bv.x, acc[mt][nt][1] + bv.y);
                    *(uint32_t*)&g_k_h[o + 8 * HD] =
                        packh(acc[mt][nt][2] + bv.x, acc[mt][nt][3] + bv.y);
                }
            }
        } else {
            // v: bounce fp32 via smem, transpose, write g_vT hi only [d][n]
            float* Ds = smem_f;                  // [128][129]
            __syncthreads();
            #pragma unroll
            for (int mt = 0; mt < 2; mt++) {
                int ml = wm * 32 + mt * 16 + r;
                #pragma unroll
                for (int nt = 0; nt < 4; nt++) {
                    int el = wn * 32 + nt * 8 + c2;
                    float2 bv = *(const float2*)&bias[n0 + el];
                    Ds[ml * 129 + el]           = acc[mt][nt][0] + bv.x;
                    Ds[ml * 129 + el + 1]       = acc[mt][nt][1] + bv.y;
                    Ds[(ml + 8) * 129 + el]     = acc[mt][nt][2] + bv.x;
                    Ds[(ml + 8) * 129 + el + 1] = acc[mt][nt][3] + bv.y;
                }
            }
            __syncthreads();
            int e  = t >> 2;                     // d index within tile (0..127)
            int mh = (t & 3) * 32;               // n quarter
            int dg = (n0 & 1023) + e;
            int h = dg >> 6, d = dg & 63;
            int bb_ = m0 >> 11, nloc = m0 & 2047;
            size_t ob = ((size_t)((bb_ * HEADS + h) * HD + d)) * SEQ + nloc + mh;
            #pragma unroll 4
            for (int i = 0; i < 32; i += 4) {
                uint2 vh = { packh(Ds[(mh + i) * 129 + e],     Ds[(mh + i + 1) * 129 + e]),
                             packh(Ds[(mh + i + 2) * 129 + e], Ds[(mh + i + 3) * 129 + e]) };
                *(uint2*)&g_vT_h[ob + i] = vh;
            }
        }
    }
}

// ---------------------------------------------------------------------------
// Flash attention: QK 2-term fp16, PV 1-term (P in [0,1], fp16-exact enough).
// CTA = 64 q-rows (4 warps), j-tile 64. SMEM: Qh+Ql 16KB; (Kh+Vh 16KB) x2.
// 48KB total -> 3 CTAs/SM. Epilogue writes g_ao hi only.
// ---------------------------------------------------------------------------
#define F_SMEM (16384 + 2 * 16384)   // 48KB

__global__ __launch_bounds__(128, 1) void flash_kernel()
{
    extern __shared__ float fs[];
    const uint32_t base = smem_u32(fs);
    const uint32_t Qh = base, Ql = base + 8192;
    const uint32_t St = base + 16384;            // stages

    const int t = threadIdx.x, lane = t & 31, w = t >> 5;
    const int bh = blockIdx.x, i0 = blockIdx.y;
    const int r = lane >> 2, q = lane & 3;

    // Q tile (once)
    {
        const __half* qh = g_q_h + ((size_t)bh * SEQ + i0 * 64) * HD;
        const __half* ql = g_q_l + ((size_t)bh * SEQ + i0 * 64) * HD;
        #pragma unroll
        for (int i = 0; i < 4; i++) {
            int u = t + i * 128;
            int rr = u >> 3, c = u & 7;
            uint32_t sw = sw128((uint32_t)(rr * 128 + c * 16));
            cp16(Qh + sw, qh + (size_t)rr * HD + c * 8);
            cp16(Ql + sw, ql + (size_t)rr * HD + c * 8);
        }
        CP_COMMIT();
    }
    auto loadKV = [&](int j) {
        uint32_t S = St + (j & 1) * 16384;
        const __half* kh = g_k_h  + ((size_t)bh * SEQ + j * 64) * HD;
        const __half* vh = g_vT_h + (size_t)bh * HD * SEQ + j * 64;
        #pragma unroll
        for (int i = 0; i < 4; i++) {
            int u = t + i * 128;
            int rr = u >> 3, c = u & 7;
            uint32_t sw = sw128((uint32_t)(rr * 128 + c * 16));
            cp16(S + sw,        kh + (size_t)rr * HD + c * 8);
            cp16(S + 8192 + sw, vh + (size_t)rr * SEQ + c * 8);
        }
        CP_COMMIT();
    };
    loadKV(0);

    float oacc[8][4];
    #pragma unroll
    for (int d = 0; d < 8; d++)
        #pragma unroll
        for (int i = 0; i < 4; i++) oacc[d][i] = 0.0f;
    float mrow[2] = { -CUDART_INF_F, -CUDART_INF_F };
    float lrow[2] = { 0.0f, 0.0f };

    for (int j = 0; j < SEQ / 64; ++j) {
        if (j + 1 < SEQ / 64) { loadKV(j + 1); CP_WAIT(1); }
        else                  { CP_WAIT(0); }
        __syncthreads();
        const uint32_t sK = St + (j & 1) * 16384;
        const uint32_t sV = sK + 8192;

        // ---- S = (Qh+Ql) Kh^T (scale folded into Q), term-major ----
        float sacc[8][4];
        #pragma unroll
        for (int nt = 0; nt < 8; nt++)
            #pragma unroll
            for (int i = 0; i < 4; i++) sacc[nt][i] = 0.0f;

        #pragma unroll
        for (int cc = 0; cc < 4; ++cc) {        // k16 over d=64
            uint32_t ah[4], al[4];
            {
                int row = w * 16 + (lane & 15);
                uint32_t bc = cc * 32 + (lane >> 4) * 16;
                ldsm4(ah[0], ah[1], ah[2], ah[3], Qh + sw128((uint32_t)(row * 128) + bc));
                ldsm4(al[0], al[1], al[2], al[3], Ql + sw128((uint32_t)(row * 128) + bc));
            }
            uint32_t kbh[4][4];
            #pragma unroll
            for (int g = 0; g < 4; g++) {
                int row = g * 16 + (lane & 7) + ((lane & 16) ? 8 : 0);
                uint32_t bc = cc * 32 + ((lane & 8) ? 16 : 0);
                ldsm4(kbh[g][0], kbh[g][1], kbh[g][2], kbh[g][3],
                      sK + sw128((uint32_t)(row * 128) + bc));
            }
            #pragma unroll
            for (int g = 0; g < 4; g++) {
                mma16(sacc[2*g],     ah, kbh[g]);
                mma16(sacc[2*g + 1], ah, kbh[g] + 2);
            }
            #pragma unroll
            for (int g = 0; g < 4; g++) {
                mma16(sacc[2*g],     al, kbh[g]);
                mma16(sacc[2*g + 1], al, kbh[g] + 2);
            }
        }

        // ---- online softmax ----
        #pragma unroll
        for (int rp = 0; rp < 2; rp++) {
            const int lo = rp * 2;
            float mx = -CUDART_INF_F;
            #pragma unroll
            for (int nt = 0; nt < 8; nt++)
                mx = fmaxf(mx, fmaxf(sacc[nt][lo], sacc[nt][lo + 1]));
            mx = fmaxf(mx, __shfl_xor_sync(0xffffffffu, mx, 1));
            mx = fmaxf(mx, __shfl_xor_sync(0xffffffffu, mx, 2));
            float mn = fmaxf(mrow[rp], mx);
            float corr = __expf(mrow[rp] - mn);
            mrow[rp] = mn;
            float sum = 0.0f;
            #pragma unroll
            for (int nt = 0; nt < 8; nt++) {
                float p0 = __expf(sacc[nt][lo] - mn);
                float p1 = __expf(sacc[nt][lo + 1] - mn);
                sacc[nt][lo] = p0; sacc[nt][lo + 1] = p1;
                sum += p0 + p1;
            }
            sum += __shfl_xor_sync(0xffffffffu, sum, 1);
            sum += __shfl_xor_sync(0xffffffffu, sum, 2);
            lrow[rp] = lrow[rp] * corr + sum;
            #pragma unroll
            for (int d = 0; d < 8; d++) {
                oacc[d][lo]     *= corr;
                oacc[d][lo + 1] *= corr;
            }
        }

        // ---- O += P Vh  (P 1-term fp16; term-major over 8 accs) ----
        #pragma unroll
        for (int kc = 0; kc < 4; ++kc) {        // k16 over 64 keys
            uint32_t ph[4];
            ph[0] = packh(sacc[2*kc][0],     sacc[2*kc][1]);
            ph[1] = packh(sacc[2*kc][2],     sacc[2*kc][3]);
            ph[2] = packh(sacc[2*kc + 1][0], sacc[2*kc + 1][1]);
            ph[3] = packh(sacc[2*kc + 1][2], sacc[2*kc + 1][3]);
            uint32_t vbh[4][4];
            #pragma unroll
            for (int g = 0; g < 4; g++) {
                int row = g * 16 + (lane & 7) + ((lane & 16) ? 8 : 0);
                uint32_t bc = kc * 32 + ((lane & 8) ? 16 : 0);
                ldsm4(vbh[g][0], vbh[g][1], vbh[g][2], vbh[g][3],
                      sV + sw128((uint32_t)(row * 128) + bc));
            }
            #pragma unroll
            for (int g = 0; g < 4; g++) {
                mma16(oacc[2*g],     ph, vbh[g]);
                mma16(oacc[2*g + 1], ph, vbh[g] + 2);
            }
        }
        __syncthreads();
    }

    // ---- write O (f16 hi only) ----
    const int bb = bh >> 4, h = bh & 15;
    #pragma unroll
    for (int rp = 0; rp < 2; rp++) {
        float inv = 1.0f / lrow[rp];
        int n = i0 * 64 + w * 16 + r + rp * 8;
        size_t ob = ((size_t)(bb * SEQ + n)) * DIMM + h * 64;
        #pragma unroll
        for (int d = 0; d < 8; d++) {
            *(uint32_t*)&g_ao_h[ob + d * 8 + q * 2] =
                packh(oacc[d][rp * 2] * inv, oacc[d][rp * 2 + 1] * inv);
        }
    }
}

// ---------------------------------------------------------------------------
extern "C" void kernel_launch(void* const* d_in, const int* in_sizes, int n_in,
                              void* d_out, int out_size)
{
    const float* x     = (const float*)d_in[0];
    const float* W_qkv = (const float*)d_in[1];
    const float* b_qkv = (const float*)d_in[2];
    const float* W_out = (const float*)d_in[3];
    const float* b_out = (const float*)d_in[4];
    float* out = (float*)d_out;

    cudaFuncSetAttribute((const void*)gemm_tc<0,2>, cudaFuncAttributeMaxDynamicSharedMemorySize, GEMM_SMEM);
    cudaFuncSetAttribute((const void*)gemm_tc<0,1>, cudaFuncAttributeMaxDynamicSharedMemorySize, GEMM_SMEM);
    cudaFuncSetAttribute((const void*)gemm_tc<1,1>, cudaFuncAttributeMaxDynamicSharedMemorySize, GEMM_SMEM);
    cudaFuncSetAttribute(flash_kernel, cudaFuncAttributeMaxDynamicSharedMemorySize, F_SMEM);

    __half *xh, *xl, *wqh, *woh, *aoh;
    cudaGetSymbolAddress((void**)&xh,  g_x_h);  cudaGetSymbolAddress((void**)&xl,  g_x_l);
    cudaGetSymbolAddress((void**)&wqh, g_wq_h);
    cudaGetSymbolAddress((void**)&woh, g_wo_h);
    cudaGetSymbolAddress((void**)&aoh, g_ao_h);

    split_hl_kernel<<<(MROWS*DIMM/4 + 255)/256, 256>>>(x,     xh, xl, MROWS*DIMM/4);
    split_h_kernel <<<(QKVN*DIMM/4 + 255)/256, 256>>>(W_qkv, wqh,     QKVN*DIMM/4);
    split_h_kernel <<<(DIMM*DIMM/4 + 255)/256, 256>>>(W_out, woh,     DIMM*DIMM/4);

    // QKV projection, split by precision need:
    //   q columns (0..1023):   2-term A (feeds softmax logits, stored hi/lo)
    //   k,v columns (1024..):  1-term A (outputs stored as plain fp16 anyway)
    gemm_tc<0,2><<<dim3(DIMM/128,          MROWS/128), 512, GEMM_SMEM>>>(xh, xl, wqh, b_qkv, nullptr, 0);
    gemm_tc<0,1><<<dim3((QKVN-DIMM)/128,   MROWS/128), 512, GEMM_SMEM>>>(xh, nullptr, wqh, b_qkv, nullptr, DIMM);
    flash_kernel<<<dim3(BH, SEQ/64), 128, F_SMEM>>>();
    gemm_tc<1,1><<<dim3(DIMM/128, MROWS/128), 512, GEMM_SMEM>>>(aoh, nullptr, woh, b_out, out, 0);
}